// round 1
// baseline (speedup 1.0000x reference)
#include <cuda_runtime.h>
#include <math.h>

// Problem constants
#define BATCH   2
#define S_LEN   2048
#define D_DIM   2048
#define NH      16
#define HD      128
#define LAT     512
#define ROWS_TOT (BATCH * S_LEN)   // 4096

// Scratch (allocation-free rule: __device__ globals)
__device__ float g_Q[BATCH * S_LEN * D_DIM];   // [b,s,h,hd] == [rows, D]
__device__ float g_K[BATCH * S_LEN * D_DIM];
__device__ float g_V[BATCH * S_LEN * D_DIM];
__device__ float g_C[BATCH * S_LEN * LAT];     // latent c_kv
__device__ float g_A[BATCH * S_LEN * D_DIM];   // attention output pre-Wo

// ---------------------------------------------------------------------------
// SGEMM: C[M,N] = A[M,K] @ B[K,N], row-major, all dims % {128,8} == 0.
// 128x128 block tile, BK=8, 256 threads, 8x8 register microtile.
// ---------------------------------------------------------------------------
__global__ __launch_bounds__(256) void sgemm_kernel(
    const float* __restrict__ A, const float* __restrict__ B,
    float* __restrict__ C, int M, int N, int K)
{
    constexpr int BM = 128, BN = 128, BK = 8, TM = 8, TN = 8;
    __shared__ float As[BK][BM];
    __shared__ float Bs[BK][BN];

    const int tid  = threadIdx.x;
    const int tx   = tid & 15;       // 0..15 (N direction)
    const int ty   = tid >> 4;       // 0..15 (M direction)
    const int aRow = tid >> 1;       // 0..127
    const int aCol = (tid & 1) << 2; // 0 or 4
    const int bRow = tid >> 5;       // 0..7
    const int bCol = (tid & 31) << 2;// 0..124

    const float* Ap = A + (size_t)(blockIdx.y * BM) * K;
    const float* Bp = B + (size_t)(blockIdx.x * BN);

    float acc[TM][TN];
#pragma unroll
    for (int i = 0; i < TM; i++)
#pragma unroll
        for (int j = 0; j < TN; j++) acc[i][j] = 0.f;

    for (int k0 = 0; k0 < K; k0 += BK) {
        float4 a4 = *(const float4*)(Ap + (size_t)aRow * K + k0 + aCol);
        float4 b4 = *(const float4*)(Bp + (size_t)(k0 + bRow) * N + bCol);
        As[aCol + 0][aRow] = a4.x;
        As[aCol + 1][aRow] = a4.y;
        As[aCol + 2][aRow] = a4.z;
        As[aCol + 3][aRow] = a4.w;
        *(float4*)&Bs[bRow][bCol] = b4;
        __syncthreads();

#pragma unroll
        for (int kk = 0; kk < BK; kk++) {
            float ar[TM], br[TN];
            *(float4*)&ar[0] = *(const float4*)&As[kk][ty * TM];
            *(float4*)&ar[4] = *(const float4*)&As[kk][ty * TM + 4];
            *(float4*)&br[0] = *(const float4*)&Bs[kk][tx * TN];
            *(float4*)&br[4] = *(const float4*)&Bs[kk][tx * TN + 4];
#pragma unroll
            for (int i = 0; i < TM; i++)
#pragma unroll
                for (int j = 0; j < TN; j++)
                    acc[i][j] = fmaf(ar[i], br[j], acc[i][j]);
        }
        __syncthreads();
    }

    float* Cp = C + (size_t)(blockIdx.y * BM + ty * TM) * N
                  + (size_t)blockIdx.x * BN + tx * TN;
#pragma unroll
    for (int i = 0; i < TM; i++) {
#pragma unroll
        for (int j = 0; j < TN; j += 4) {
            float4 v = make_float4(acc[i][j], acc[i][j + 1],
                                   acc[i][j + 2], acc[i][j + 3]);
            *(float4*)(Cp + (size_t)i * N + j) = v;
        }
    }
}

// ---------------------------------------------------------------------------
// RoPE applied in place to Q and K. One thread per (b,s,h,pair).
// element layout: idx enumerates ((b*S+s)*H+h)*64 + p; floats at 2*idx, 2*idx+1
// ---------------------------------------------------------------------------
__global__ void rope_kernel(float* __restrict__ Q, float* __restrict__ K,
                            const float* __restrict__ freqs)
{
    const int total = BATCH * S_LEN * NH * (HD / 2);
    int idx = blockIdx.x * blockDim.x + threadIdx.x;
    if (idx >= total) return;
    int p = idx & 63;                       // pair index within head
    int s = (idx >> 10) & (S_LEN - 1);      // / (64*16) % S
    float f = freqs[s * (HD / 2) + p];
    float sn, cs;
    sincosf(f, &sn, &cs);
    float2* Q2 = (float2*)Q;
    float2* K2 = (float2*)K;
    float2 q = Q2[idx];
    Q2[idx] = make_float2(q.x * cs - q.y * sn, q.x * sn + q.y * cs);
    float2 k = K2[idx];
    K2[idx] = make_float2(k.x * cs - k.y * sn, k.x * sn + k.y * cs);
}

// ---------------------------------------------------------------------------
// Causal flash attention, fp32. Br=Bc=64, 256 threads.
// Score microtile 4x4 (16x16 thread grid); PV output microtile 4x8.
// Shared (dynamic, 112KB): Qs[HD][64] K^T-style, Ks[HD][64], Vs[64][HD],
// Ps[64][64] (P transposed for the PV GEMM).
// Mask is exactly causal: exp(-1e30 - m) == 0 in fp32 => identical to ref.
// ---------------------------------------------------------------------------
#define BR 64
#define BC 64

__global__ __launch_bounds__(256) void flash_kernel(
    const float* __restrict__ Q, const float* __restrict__ K,
    const float* __restrict__ V, float* __restrict__ O)
{
    extern __shared__ float sm[];
    float* Qs = sm;                    // HD*BR
    float* Ks = Qs + HD * BR;          // HD*BC
    float* Vs = Ks + HD * BC;          // BC*HD
    float* Ps = Vs + BC * HD;          // BC*BR

    const int bh = blockIdx.y;
    const int b = bh >> 4, h = bh & 15;
    const int q0 = blockIdx.x * BR;
    const int rs = NH * HD;            // 2048 floats between rows (same b)
    const size_t base = ((size_t)b * S_LEN * NH + h) * HD;
    const float* Qb = Q + base;
    const float* Kb = K + base;
    const float* Vb = V + base;
    float* Ob = O + base;

    const int tid = threadIdx.x;
    const int tx = tid & 15, ty = tid >> 4;

    // Load Q tile transposed into Qs[d][r]
    for (int i = tid; i < BR * (HD / 4); i += 256) {
        int r  = i >> 5;           // / (HD/4)
        int c4 = (i & 31) << 2;
        float4 v = *(const float4*)(Qb + (size_t)(q0 + r) * rs + c4);
        Qs[(c4 + 0) * BR + r] = v.x;
        Qs[(c4 + 1) * BR + r] = v.y;
        Qs[(c4 + 2) * BR + r] = v.z;
        Qs[(c4 + 3) * BR + r] = v.w;
    }

    float m[4], l[4], acc[4][8];
#pragma unroll
    for (int i = 0; i < 4; i++) {
        m[i] = -1e30f; l[i] = 0.f;
#pragma unroll
        for (int j = 0; j < 8; j++) acc[i][j] = 0.f;
    }

    const float scale = 0.08838834764831845f;  // 1/sqrt(128)
    const int kend = q0 + BR;                  // causal bound

    for (int k0 = 0; k0 < kend; k0 += BC) {
        __syncthreads();   // previous iter's reads of Ks/Vs/Ps complete
        for (int i = tid; i < BC * (HD / 4); i += 256) {
            int r  = i >> 5;
            int c4 = (i & 31) << 2;
            float4 kv = *(const float4*)(Kb + (size_t)(k0 + r) * rs + c4);
            Ks[(c4 + 0) * BC + r] = kv.x;
            Ks[(c4 + 1) * BC + r] = kv.y;
            Ks[(c4 + 2) * BC + r] = kv.z;
            Ks[(c4 + 3) * BC + r] = kv.w;
            float4 vv = *(const float4*)(Vb + (size_t)(k0 + r) * rs + c4);
            *(float4*)&Vs[r * HD + c4] = vv;
        }
        __syncthreads();

        // S tile: s4[i][j] = Q[ty*4+i] . K[tx*4+j]
        float s4[4][4];
#pragma unroll
        for (int i = 0; i < 4; i++)
#pragma unroll
            for (int j = 0; j < 4; j++) s4[i][j] = 0.f;

#pragma unroll 4
        for (int d = 0; d < HD; d++) {
            float qr[4], kr[4];
            *(float4*)qr = *(const float4*)&Qs[d * BR + ty * 4];
            *(float4*)kr = *(const float4*)&Ks[d * BC + tx * 4];
#pragma unroll
            for (int i = 0; i < 4; i++)
#pragma unroll
                for (int j = 0; j < 4; j++)
                    s4[i][j] = fmaf(qr[i], kr[j], s4[i][j]);
        }

        const bool diag = (k0 + BC > q0);
#pragma unroll
        for (int i = 0; i < 4; i++) {
            const int qg = q0 + ty * 4 + i;
#pragma unroll
            for (int j = 0; j < 4; j++) {
                float v = s4[i][j] * scale;
                if (diag && (k0 + tx * 4 + j) > qg) v = -1e30f;
                s4[i][j] = v;
            }
        }

        // Online softmax per row (reduce across the 16 tx threads = half warp)
#pragma unroll
        for (int i = 0; i < 4; i++) {
            float mt = fmaxf(fmaxf(s4[i][0], s4[i][1]),
                             fmaxf(s4[i][2], s4[i][3]));
#pragma unroll
            for (int off = 1; off < 16; off <<= 1)
                mt = fmaxf(mt, __shfl_xor_sync(0xffffffffu, mt, off));
            float mn = fmaxf(m[i], mt);
            float alpha = __expf(m[i] - mn);
            float lt = 0.f;
#pragma unroll
            for (int j = 0; j < 4; j++) {
                s4[i][j] = __expf(s4[i][j] - mn);
                lt += s4[i][j];
            }
#pragma unroll
            for (int off = 1; off < 16; off <<= 1)
                lt += __shfl_xor_sync(0xffffffffu, lt, off);
            m[i] = mn;
            l[i] = l[i] * alpha + lt;
#pragma unroll
            for (int j = 0; j < 8; j++) acc[i][j] *= alpha;
        }

        // Stage P transposed: Ps[k][q]
#pragma unroll
        for (int j = 0; j < 4; j++)
#pragma unroll
            for (int i = 0; i < 4; i++)
                Ps[(tx * 4 + j) * BR + ty * 4 + i] = s4[i][j];
        __syncthreads();

        // PV: acc[i][j] += sum_k Ps[k][ty*4+i] * Vs[k][tx*8+j]
#pragma unroll 2
        for (int kk = 0; kk < BC; kk++) {
            float pr[4], vr[8];
            *(float4*)pr      = *(const float4*)&Ps[kk * BR + ty * 4];
            *(float4*)&vr[0]  = *(const float4*)&Vs[kk * HD + tx * 8];
            *(float4*)&vr[4]  = *(const float4*)&Vs[kk * HD + tx * 8 + 4];
#pragma unroll
            for (int i = 0; i < 4; i++)
#pragma unroll
                for (int j = 0; j < 8; j++)
                    acc[i][j] = fmaf(pr[i], vr[j], acc[i][j]);
        }
    }

    // Epilogue: normalize, write to [b, q, h, d] layout
#pragma unroll
    for (int i = 0; i < 4; i++) {
        float inv = 1.0f / l[i];
        float* Op = Ob + (size_t)(q0 + ty * 4 + i) * rs + tx * 8;
#pragma unroll
        for (int j = 0; j < 8; j += 4) {
            float4 v = make_float4(acc[i][j] * inv, acc[i][j + 1] * inv,
                                   acc[i][j + 2] * inv, acc[i][j + 3] * inv);
            *(float4*)(Op + j) = v;
        }
    }
}

// ---------------------------------------------------------------------------
// Launch: x@Wq, x@Wdown, c@Wkup, c@Wvup, RoPE(Q,K), flash attn, attn@Wo
// Inputs (metadata order): x, freqs, mask, Wq, Wdown, Wkup, Wvup, Wo
// mask is unused: it is exactly the causal mask, handled inside flash_kernel.
// ---------------------------------------------------------------------------
extern "C" void kernel_launch(void* const* d_in, const int* in_sizes, int n_in,
                              void* d_out, int out_size)
{
    const float* x     = (const float*)d_in[0];
    const float* freqs = (const float*)d_in[1];
    const float* Wq    = (const float*)d_in[3];
    const float* Wdn   = (const float*)d_in[4];
    const float* Wku   = (const float*)d_in[5];
    const float* Wvu   = (const float*)d_in[6];
    const float* Wo    = (const float*)d_in[7];
    float* out = (float*)d_out;

    float *Qb, *Kb, *Vb, *Cb, *Ab;
    cudaGetSymbolAddress((void**)&Qb, g_Q);
    cudaGetSymbolAddress((void**)&Kb, g_K);
    cudaGetSymbolAddress((void**)&Vb, g_V);
    cudaGetSymbolAddress((void**)&Cb, g_C);
    cudaGetSymbolAddress((void**)&Ab, g_A);

    dim3 blk(256);

    // Projections
    sgemm_kernel<<<dim3(D_DIM / 128, ROWS_TOT / 128), blk>>>(
        x, Wq, Qb, ROWS_TOT, D_DIM, D_DIM);
    sgemm_kernel<<<dim3(LAT / 128, ROWS_TOT / 128), blk>>>(
        x, Wdn, Cb, ROWS_TOT, LAT, D_DIM);
    sgemm_kernel<<<dim3(D_DIM / 128, ROWS_TOT / 128), blk>>>(
        Cb, Wku, Kb, ROWS_TOT, D_DIM, LAT);
    sgemm_kernel<<<dim3(D_DIM / 128, ROWS_TOT / 128), blk>>>(
        Cb, Wvu, Vb, ROWS_TOT, D_DIM, LAT);

    // RoPE on Q and K
    const int pairs = BATCH * S_LEN * NH * (HD / 2);
    rope_kernel<<<(pairs + 255) / 256, 256>>>(Qb, Kb, freqs);

    // Flash attention (causal)
    size_t smem = (size_t)(HD * BR + HD * BC + BC * HD + BC * BR) * sizeof(float);
    cudaFuncSetAttribute(flash_kernel,
                         cudaFuncAttributeMaxDynamicSharedMemorySize, (int)smem);
    flash_kernel<<<dim3(S_LEN / BR, BATCH * NH), blk, smem>>>(Qb, Kb, Vb, Ab);

    // Output projection
    sgemm_kernel<<<dim3(D_DIM / 128, ROWS_TOT / 128), blk>>>(
        Ab, Wo, out, ROWS_TOT, D_DIM, D_DIM);
}

// round 3
// speedup vs baseline: 1.4693x; 1.4693x over previous
#include <cuda_runtime.h>
#include <cuda_bf16.h>
#include <cstdint>
#include <math.h>

// Problem constants
#define BATCH   2
#define S_LEN   2048
#define D_DIM   2048
#define NH      16
#define HD      128
#define LAT     512
#define ROWS_TOT (BATCH * S_LEN)   // 4096

// ---------------------------------------------------------------------------
// Scratch (__device__ globals; allocation-free rule)
// ---------------------------------------------------------------------------
__device__ float g_Q[ROWS_TOT * D_DIM];
__device__ float g_K[ROWS_TOT * D_DIM];
__device__ float g_V[ROWS_TOT * D_DIM];
__device__ float g_A[ROWS_TOT * D_DIM];

__device__ __nv_bfloat16 g_xhi[ROWS_TOT * D_DIM];
__device__ __nv_bfloat16 g_xlo[ROWS_TOT * D_DIM];
__device__ __nv_bfloat16 g_ahi[ROWS_TOT * D_DIM];
__device__ __nv_bfloat16 g_alo[ROWS_TOT * D_DIM];
__device__ __nv_bfloat16 g_chi[ROWS_TOT * LAT];
__device__ __nv_bfloat16 g_clo[ROWS_TOT * LAT];

// Transposed-weight pool ([N,K] K-major bf16), hi and lo parts.
#define OFF_WQ  0
#define OFF_WDN 4194304
#define OFF_WKU 5242880
#define OFF_WVU 6291456
#define OFF_WO  7340032
#define WT_TOTAL 11534336
__device__ __nv_bfloat16 g_wthi[WT_TOTAL];
__device__ __nv_bfloat16 g_wtlo[WT_TOTAL];

// ---------------------------------------------------------------------------
// PTX helpers (sm_80+ features only — harness targets plain sm_103)
// ---------------------------------------------------------------------------
__device__ __forceinline__ uint32_t smem_u32(const void* p) {
    uint32_t a;
    asm("{ .reg .u64 t; cvta.to.shared.u64 t, %1; cvt.u32.u64 %0, t; }"
        : "=r"(a) : "l"(p));
    return a;
}
__device__ __forceinline__ void cp16(uint32_t dst, const void* src) {
    asm volatile("cp.async.cg.shared.global [%0], [%1], 16;" :: "r"(dst), "l"(src));
}
#define CP_COMMIT() asm volatile("cp.async.commit_group;" ::: "memory")

__device__ __forceinline__ void ldsm4(uint32_t& r0, uint32_t& r1,
                                      uint32_t& r2, uint32_t& r3, uint32_t a) {
    asm volatile("ldmatrix.sync.aligned.m8n8.x4.shared.b16 {%0,%1,%2,%3}, [%4];"
                 : "=r"(r0), "=r"(r1), "=r"(r2), "=r"(r3) : "r"(a));
}
__device__ __forceinline__ void mma16816(float* d, const uint32_t* a,
                                         uint32_t b0, uint32_t b1) {
    asm volatile(
        "mma.sync.aligned.m16n8k16.row.col.f32.bf16.bf16.f32 "
        "{%0,%1,%2,%3}, {%4,%5,%6,%7}, {%8,%9}, {%0,%1,%2,%3};"
        : "+f"(d[0]), "+f"(d[1]), "+f"(d[2]), "+f"(d[3])
        : "r"(a[0]), "r"(a[1]), "r"(a[2]), "r"(a[3]), "r"(b0), "r"(b1));
}

// ---------------------------------------------------------------------------
// HMMA bf16 hi/lo GEMM: C[M,N] = A[M,K] @ Bt[N,K]^T, fp32 accumulation.
// A as Ahi/Alo [M,K] row-major bf16; Bt as Bhi/Blo [N,K] row-major bf16.
// 128x128x32 tiles, 256 thr (8 warps, 4x2), double-buffered cp.async,
// ldmatrix from 80B-pitch SMEM (conflict-free), 3-term hi/lo accumulation.
// ---------------------------------------------------------------------------
#define TILE_B  10240          // 128 rows x 80 bytes
#define ST_AHI  0
#define ST_ALO  10240
#define ST_BHI  20480
#define ST_BLO  30720
#define STAGE_B 40960
#define GK_SMEM_DYN (2 * STAGE_B)   // 80 KB

__global__ __launch_bounds__(256, 1)
void gemm_hilo_kernel(const __nv_bfloat16* __restrict__ Ahi,
                      const __nv_bfloat16* __restrict__ Alo,
                      const __nv_bfloat16* __restrict__ Bhi,
                      const __nv_bfloat16* __restrict__ Blo,
                      float* __restrict__ Cout,
                      __nv_bfloat16* __restrict__ Chi,
                      __nv_bfloat16* __restrict__ Clo,
                      int M, int N, int K)
{
    extern __shared__ char dsm[];
    const uint32_t sbase = smem_u32(dsm);
    const int tid = threadIdx.x, lane = tid & 31, wid = tid >> 5;
    const int wm = wid & 3, wn = wid >> 2;
    const int m0 = blockIdx.y * 128, n0 = blockIdx.x * 128;

    const __nv_bfloat16* gAh = Ahi + (size_t)m0 * K;
    const __nv_bfloat16* gAl = Alo + (size_t)m0 * K;
    const __nv_bfloat16* gBh = Bhi + (size_t)n0 * K;
    const __nv_bfloat16* gBl = Blo + (size_t)n0 * K;

    const int lrow = tid >> 1;           // 0..127
    const int lc0  = (tid & 1) * 2;      // 0 or 2 (16B column index)

    float acc[2][8][4];
#pragma unroll
    for (int mt = 0; mt < 2; mt++)
#pragma unroll
        for (int nt = 0; nt < 8; nt++)
#pragma unroll
            for (int r = 0; r < 4; r++) acc[mt][nt][r] = 0.f;

    const int nk = K >> 5;

    // ---- stage loader (cp.async; 2x16B per thread per tile) ----
    auto load_stage = [&](int buf, int kc) {
        const uint32_t st = sbase + buf * STAGE_B;
        const size_t koff = (size_t)kc * 32;
#pragma unroll
        for (int t = 0; t < 2; t++) {
            const int c16 = lc0 + t;
            const uint32_t doff = lrow * 80 + c16 * 16;
            const size_t soff = (size_t)lrow * K + koff + c16 * 8;
            cp16(st + ST_AHI + doff, gAh + soff);
            cp16(st + ST_ALO + doff, gAl + soff);
            cp16(st + ST_BHI + doff, gBh + soff);
            cp16(st + ST_BLO + doff, gBl + soff);
        }
        CP_COMMIT();
    };

    load_stage(0, 0);

    for (int k = 0; k < nk; k++) {
        if (k + 1 < nk) {
            load_stage((k + 1) & 1, k + 1);
            asm volatile("cp.async.wait_group 1;" ::: "memory");
        } else {
            asm volatile("cp.async.wait_group 0;" ::: "memory");
        }
        __syncthreads();

        const uint32_t st = sbase + (k & 1) * STAGE_B;
#pragma unroll
        for (int ks = 0; ks < 2; ks++) {
            uint32_t ah[2][4], al[2][4];
#pragma unroll
            for (int mt = 0; mt < 2; mt++) {
                const int row = wm * 32 + mt * 16 + (lane & 15);
                const uint32_t off = row * 80 + ks * 32 + ((lane >> 4) << 4);
                ldsm4(ah[mt][0], ah[mt][1], ah[mt][2], ah[mt][3],
                      st + ST_AHI + off);
                ldsm4(al[mt][0], al[mt][1], al[mt][2], al[mt][3],
                      st + ST_ALO + off);
            }
#pragma unroll
            for (int bp = 0; bp < 4; bp++) {
                const int rn = wn * 64 + bp * 16 + ((lane >> 4) << 3) + (lane & 7);
                const uint32_t off = rn * 80 + ks * 32 + (((lane >> 3) & 1) << 4);
                uint32_t bh[4], bl[4];
                ldsm4(bh[0], bh[1], bh[2], bh[3], st + ST_BHI + off);
                ldsm4(bl[0], bl[1], bl[2], bl[3], st + ST_BLO + off);
#pragma unroll
                for (int mt = 0; mt < 2; mt++) {
#pragma unroll
                    for (int h = 0; h < 2; h++) {
                        float* d = acc[mt][2 * bp + h];
                        mma16816(d, ah[mt], bh[2 * h], bh[2 * h + 1]);
                        mma16816(d, ah[mt], bl[2 * h], bl[2 * h + 1]);
                        mma16816(d, al[mt], bh[2 * h], bh[2 * h + 1]);
                    }
                }
            }
        }
        __syncthreads();
    }

    // ---- epilogue ----
    const int lr = lane >> 2, lc = (lane & 3) * 2;
    const int rbase = m0 + wm * 32, cbase = n0 + wn * 64;
    if (Cout) {
#pragma unroll
        for (int mt = 0; mt < 2; mt++) {
#pragma unroll
            for (int nt = 0; nt < 8; nt++) {
                float* d = acc[mt][nt];
                const size_t r0 = (size_t)(rbase + mt * 16 + lr) * N
                                  + cbase + nt * 8 + lc;
                *(float2*)(Cout + r0)         = make_float2(d[0], d[1]);
                *(float2*)(Cout + r0 + 8 * N) = make_float2(d[2], d[3]);
            }
        }
    } else {
#pragma unroll
        for (int mt = 0; mt < 2; mt++) {
#pragma unroll
            for (int nt = 0; nt < 8; nt++) {
                float* d = acc[mt][nt];
#pragma unroll
                for (int half = 0; half < 2; half++) {
                    float v0 = d[half * 2], v1 = d[half * 2 + 1];
                    __nv_bfloat16 h0 = __float2bfloat16(v0);
                    __nv_bfloat16 h1 = __float2bfloat16(v1);
                    __nv_bfloat16 l0 = __float2bfloat16(v0 - __bfloat162float(h0));
                    __nv_bfloat16 l1 = __float2bfloat16(v1 - __bfloat162float(h1));
                    const size_t o = (size_t)(rbase + mt * 16 + lr + half * 8) * N
                                     + cbase + nt * 8 + lc;
                    *(__nv_bfloat162*)(Chi + o) = __nv_bfloat162(h0, h1);
                    *(__nv_bfloat162*)(Clo + o) = __nv_bfloat162(l0, l1);
                }
            }
        }
    }
}

// ---------------------------------------------------------------------------
// fp32 -> bf16 hi/lo elementwise
// ---------------------------------------------------------------------------
__global__ void convert_hilo_kernel(const float* __restrict__ in,
                                    __nv_bfloat16* __restrict__ hi,
                                    __nv_bfloat16* __restrict__ lo, int n)
{
    int i = blockIdx.x * blockDim.x + threadIdx.x;
    if (i >= n) return;
    float v = in[i];
    __nv_bfloat16 h = __float2bfloat16(v);
    hi[i] = h;
    lo[i] = __float2bfloat16(v - __bfloat162float(h));
}

// ---------------------------------------------------------------------------
// W [Kd,Nd] fp32 -> Wt hi/lo [Nd,Kd] bf16 (tiled transpose)
// ---------------------------------------------------------------------------
__global__ void transpose_hilo_kernel(const float* __restrict__ W,
                                      __nv_bfloat16* __restrict__ hi,
                                      __nv_bfloat16* __restrict__ lo,
                                      int Kd, int Nd)
{
    __shared__ float t[32][33];
    const int tx = threadIdx.x, ty = threadIdx.y;
    const int k0 = blockIdx.y * 32, n0 = blockIdx.x * 32;
#pragma unroll
    for (int i = 0; i < 4; i++)
        t[ty + i * 8][tx] = W[(size_t)(k0 + ty + i * 8) * Nd + n0 + tx];
    __syncthreads();
#pragma unroll
    for (int i = 0; i < 4; i++) {
        float v = t[tx][ty + i * 8];
        __nv_bfloat16 h = __float2bfloat16(v);
        size_t o = (size_t)(n0 + ty + i * 8) * Kd + k0 + tx;
        hi[o] = h;
        lo[o] = __float2bfloat16(v - __bfloat162float(h));
    }
}

// ---------------------------------------------------------------------------
// RoPE in place on Q and K
// ---------------------------------------------------------------------------
__global__ void rope_kernel(float* __restrict__ Q, float* __restrict__ K,
                            const float* __restrict__ freqs)
{
    const int total = BATCH * S_LEN * NH * (HD / 2);
    int idx = blockIdx.x * blockDim.x + threadIdx.x;
    if (idx >= total) return;
    int p = idx & 63;
    int s = (idx >> 10) & (S_LEN - 1);
    float f = freqs[s * (HD / 2) + p];
    float sn, cs;
    sincosf(f, &sn, &cs);
    float2* Q2 = (float2*)Q;
    float2* K2 = (float2*)K;
    float2 q = Q2[idx];
    Q2[idx] = make_float2(q.x * cs - q.y * sn, q.x * sn + q.y * cs);
    float2 k = K2[idx];
    K2[idx] = make_float2(k.x * cs - k.y * sn, k.x * sn + k.y * cs);
}

// ---------------------------------------------------------------------------
// Causal flash attention, fp32 (unchanged from round 1; known-good)
// ---------------------------------------------------------------------------
#define BR 64
#define BC 64

__global__ __launch_bounds__(256) void flash_kernel(
    const float* __restrict__ Q, const float* __restrict__ K,
    const float* __restrict__ V, float* __restrict__ O)
{
    extern __shared__ float sm[];
    float* Qs = sm;
    float* Ks = Qs + HD * BR;
    float* Vs = Ks + HD * BC;
    float* Ps = Vs + BC * HD;

    const int bh = blockIdx.y;
    const int b = bh >> 4, h = bh & 15;
    const int q0 = blockIdx.x * BR;
    const int rs = NH * HD;
    const size_t base = ((size_t)b * S_LEN * NH + h) * HD;
    const float* Qb = Q + base;
    const float* Kb = K + base;
    const float* Vb = V + base;
    float* Ob = O + base;

    const int tid = threadIdx.x;
    const int tx = tid & 15, ty = tid >> 4;

    for (int i = tid; i < BR * (HD / 4); i += 256) {
        int r  = i >> 5;
        int c4 = (i & 31) << 2;
        float4 v = *(const float4*)(Qb + (size_t)(q0 + r) * rs + c4);
        Qs[(c4 + 0) * BR + r] = v.x;
        Qs[(c4 + 1) * BR + r] = v.y;
        Qs[(c4 + 2) * BR + r] = v.z;
        Qs[(c4 + 3) * BR + r] = v.w;
    }

    float m[4], l[4], acc[4][8];
#pragma unroll
    for (int i = 0; i < 4; i++) {
        m[i] = -1e30f; l[i] = 0.f;
#pragma unroll
        for (int j = 0; j < 8; j++) acc[i][j] = 0.f;
    }

    const float scale = 0.08838834764831845f;
    const int kend = q0 + BR;

    for (int k0 = 0; k0 < kend; k0 += BC) {
        __syncthreads();
        for (int i = tid; i < BC * (HD / 4); i += 256) {
            int r  = i >> 5;
            int c4 = (i & 31) << 2;
            float4 kv = *(const float4*)(Kb + (size_t)(k0 + r) * rs + c4);
            Ks[(c4 + 0) * BC + r] = kv.x;
            Ks[(c4 + 1) * BC + r] = kv.y;
            Ks[(c4 + 2) * BC + r] = kv.z;
            Ks[(c4 + 3) * BC + r] = kv.w;
            float4 vv = *(const float4*)(Vb + (size_t)(k0 + r) * rs + c4);
            *(float4*)&Vs[r * HD + c4] = vv;
        }
        __syncthreads();

        float s4[4][4];
#pragma unroll
        for (int i = 0; i < 4; i++)
#pragma unroll
            for (int j = 0; j < 4; j++) s4[i][j] = 0.f;

#pragma unroll 4
        for (int d = 0; d < HD; d++) {
            float qr[4], kr[4];
            *(float4*)qr = *(const float4*)&Qs[d * BR + ty * 4];
            *(float4*)kr = *(const float4*)&Ks[d * BC + tx * 4];
#pragma unroll
            for (int i = 0; i < 4; i++)
#pragma unroll
                for (int j = 0; j < 4; j++)
                    s4[i][j] = fmaf(qr[i], kr[j], s4[i][j]);
        }

        const bool diag = (k0 + BC > q0);
#pragma unroll
        for (int i = 0; i < 4; i++) {
            const int qg = q0 + ty * 4 + i;
#pragma unroll
            for (int j = 0; j < 4; j++) {
                float v = s4[i][j] * scale;
                if (diag && (k0 + tx * 4 + j) > qg) v = -1e30f;
                s4[i][j] = v;
            }
        }

#pragma unroll
        for (int i = 0; i < 4; i++) {
            float mt = fmaxf(fmaxf(s4[i][0], s4[i][1]),
                             fmaxf(s4[i][2], s4[i][3]));
#pragma unroll
            for (int off = 1; off < 16; off <<= 1)
                mt = fmaxf(mt, __shfl_xor_sync(0xffffffffu, mt, off));
            float mn = fmaxf(m[i], mt);
            float alpha = __expf(m[i] - mn);
            float lt = 0.f;
#pragma unroll
            for (int j = 0; j < 4; j++) {
                s4[i][j] = __expf(s4[i][j] - mn);
                lt += s4[i][j];
            }
#pragma unroll
            for (int off = 1; off < 16; off <<= 1)
                lt += __shfl_xor_sync(0xffffffffu, lt, off);
            m[i] = mn;
            l[i] = l[i] * alpha + lt;
#pragma unroll
            for (int j = 0; j < 8; j++) acc[i][j] *= alpha;
        }

#pragma unroll
        for (int j = 0; j < 4; j++)
#pragma unroll
            for (int i = 0; i < 4; i++)
                Ps[(tx * 4 + j) * BR + ty * 4 + i] = s4[i][j];
        __syncthreads();

#pragma unroll 2
        for (int kk = 0; kk < BC; kk++) {
            float pr[4], vr[8];
            *(float4*)pr      = *(const float4*)&Ps[kk * BR + ty * 4];
            *(float4*)&vr[0]  = *(const float4*)&Vs[kk * HD + tx * 8];
            *(float4*)&vr[4]  = *(const float4*)&Vs[kk * HD + tx * 8 + 4];
#pragma unroll
            for (int i = 0; i < 4; i++)
#pragma unroll
                for (int j = 0; j < 8; j++)
                    acc[i][j] = fmaf(pr[i], vr[j], acc[i][j]);
        }
    }

#pragma unroll
    for (int i = 0; i < 4; i++) {
        float inv = 1.0f / l[i];
        float* Op = Ob + (size_t)(q0 + ty * 4 + i) * rs + tx * 8;
#pragma unroll
        for (int j = 0; j < 8; j += 4) {
            float4 v = make_float4(acc[i][j] * inv, acc[i][j + 1] * inv,
                                   acc[i][j + 2] * inv, acc[i][j + 3] * inv);
            *(float4*)(Op + j) = v;
        }
    }
}

// ---------------------------------------------------------------------------
// Launch
// Inputs: x, freqs, mask(unused: exactly causal), Wq, Wdown, Wkup, Wvup, Wo
// ---------------------------------------------------------------------------
extern "C" void kernel_launch(void* const* d_in, const int* in_sizes, int n_in,
                              void* d_out, int out_size)
{
    const float* x     = (const float*)d_in[0];
    const float* freqs = (const float*)d_in[1];
    const float* Wq    = (const float*)d_in[3];
    const float* Wdn   = (const float*)d_in[4];
    const float* Wku   = (const float*)d_in[5];
    const float* Wvu   = (const float*)d_in[6];
    const float* Wo    = (const float*)d_in[7];
    float* out = (float*)d_out;

    float *Qb, *Kb, *Vb, *Ab;
    __nv_bfloat16 *xhi, *xlo, *ahi, *alo, *chi, *clo, *wthi, *wtlo;
    cudaGetSymbolAddress((void**)&Qb, g_Q);
    cudaGetSymbolAddress((void**)&Kb, g_K);
    cudaGetSymbolAddress((void**)&Vb, g_V);
    cudaGetSymbolAddress((void**)&Ab, g_A);
    cudaGetSymbolAddress((void**)&xhi, g_xhi);
    cudaGetSymbolAddress((void**)&xlo, g_xlo);
    cudaGetSymbolAddress((void**)&ahi, g_ahi);
    cudaGetSymbolAddress((void**)&alo, g_alo);
    cudaGetSymbolAddress((void**)&chi, g_chi);
    cudaGetSymbolAddress((void**)&clo, g_clo);
    cudaGetSymbolAddress((void**)&wthi, g_wthi);
    cudaGetSymbolAddress((void**)&wtlo, g_wtlo);

    cudaFuncSetAttribute(gemm_hilo_kernel,
                         cudaFuncAttributeMaxDynamicSharedMemorySize, GK_SMEM_DYN);

    // Weight transposes + conversions (bandwidth-bound, ~100us total)
    dim3 tb(32, 8);
    transpose_hilo_kernel<<<dim3(64, 64), tb>>>(Wq,  wthi + OFF_WQ,  wtlo + OFF_WQ,  2048, 2048);
    transpose_hilo_kernel<<<dim3(16, 64), tb>>>(Wdn, wthi + OFF_WDN, wtlo + OFF_WDN, 2048, 512);
    transpose_hilo_kernel<<<dim3(64, 16), tb>>>(Wku, wthi + OFF_WKU, wtlo + OFF_WKU, 512, 2048);
    transpose_hilo_kernel<<<dim3(64, 16), tb>>>(Wvu, wthi + OFF_WVU, wtlo + OFF_WVU, 512, 2048);
    transpose_hilo_kernel<<<dim3(64, 64), tb>>>(Wo,  wthi + OFF_WO,  wtlo + OFF_WO,  2048, 2048);

    const int nx = ROWS_TOT * D_DIM;
    convert_hilo_kernel<<<nx / 256, 256>>>(x, xhi, xlo, nx);

    // Projections (HMMA bf16 hi/lo, fp32 accum)
    gemm_hilo_kernel<<<dim3(16, 32), 256, GK_SMEM_DYN>>>(
        xhi, xlo, wthi + OFF_WQ, wtlo + OFF_WQ, Qb, nullptr, nullptr,
        ROWS_TOT, D_DIM, D_DIM);
    gemm_hilo_kernel<<<dim3(4, 32), 256, GK_SMEM_DYN>>>(
        xhi, xlo, wthi + OFF_WDN, wtlo + OFF_WDN, nullptr, chi, clo,
        ROWS_TOT, LAT, D_DIM);
    gemm_hilo_kernel<<<dim3(16, 32), 256, GK_SMEM_DYN>>>(
        chi, clo, wthi + OFF_WKU, wtlo + OFF_WKU, Kb, nullptr, nullptr,
        ROWS_TOT, D_DIM, LAT);
    gemm_hilo_kernel<<<dim3(16, 32), 256, GK_SMEM_DYN>>>(
        chi, clo, wthi + OFF_WVU, wtlo + OFF_WVU, Vb, nullptr, nullptr,
        ROWS_TOT, D_DIM, LAT);

    // RoPE
    const int pairs = BATCH * S_LEN * NH * (HD / 2);
    rope_kernel<<<(pairs + 255) / 256, 256>>>(Qb, Kb, freqs);

    // Flash attention (causal, fp32)
    size_t smem = (size_t)(HD * BR + HD * BC + BC * HD + BC * BR) * sizeof(float);
    cudaFuncSetAttribute(flash_kernel,
                         cudaFuncAttributeMaxDynamicSharedMemorySize, (int)smem);
    flash_kernel<<<dim3(S_LEN / BR, BATCH * NH), 256, smem>>>(Qb, Kb, Vb, Ab);

    // Output projection
    convert_hilo_kernel<<<nx / 256, 256>>>(Ab, ahi, alo, nx);
    gemm_hilo_kernel<<<dim3(16, 32), 256, GK_SMEM_DYN>>>(
        ahi, alo, wthi + OFF_WO, wtlo + OFF_WO, out, nullptr, nullptr,
        ROWS_TOT, D_DIM, D_DIM);
}

// round 4
// speedup vs baseline: 2.8568x; 1.9443x over previous
#include <cuda_runtime.h>
#include <cuda_bf16.h>
#include <cstdint>
#include <math.h>

// Problem constants
#define BATCH   2
#define S_LEN   2048
#define D_DIM   2048
#define NH      16
#define HD      128
#define LAT     512
#define ROWS_TOT (BATCH * S_LEN)   // 4096

// ---------------------------------------------------------------------------
// Scratch (__device__ globals; allocation-free rule)
// ---------------------------------------------------------------------------
__device__ float g_Q[ROWS_TOT * D_DIM];   // fp32 Q after proj (pre-rope)
__device__ float g_K[ROWS_TOT * D_DIM];   // fp32 K after proj (pre-rope)

__device__ __nv_bfloat16 g_xhi[ROWS_TOT * D_DIM];
__device__ __nv_bfloat16 g_xlo[ROWS_TOT * D_DIM];
__device__ __nv_bfloat16 g_chi[ROWS_TOT * LAT];
__device__ __nv_bfloat16 g_clo[ROWS_TOT * LAT];
__device__ __nv_bfloat16 g_qhi[ROWS_TOT * D_DIM];
__device__ __nv_bfloat16 g_qlo[ROWS_TOT * D_DIM];
__device__ __nv_bfloat16 g_khi[ROWS_TOT * D_DIM];
__device__ __nv_bfloat16 g_klo[ROWS_TOT * D_DIM];
__device__ __nv_bfloat16 g_vhi[ROWS_TOT * D_DIM];
__device__ __nv_bfloat16 g_vlo[ROWS_TOT * D_DIM];
__device__ __nv_bfloat16 g_ohi[ROWS_TOT * D_DIM];
__device__ __nv_bfloat16 g_olo[ROWS_TOT * D_DIM];

// Transposed-weight pool ([N,K] K-major bf16), hi and lo parts.
#define OFF_WQ  0
#define OFF_WDN 4194304
#define OFF_WKU 5242880
#define OFF_WVU 6291456
#define OFF_WO  7340032
#define WT_TOTAL 11534336
__device__ __nv_bfloat16 g_wthi[WT_TOTAL];
__device__ __nv_bfloat16 g_wtlo[WT_TOTAL];

// ---------------------------------------------------------------------------
// PTX helpers (sm_80+ features only — harness targets plain sm_103)
// ---------------------------------------------------------------------------
__device__ __forceinline__ uint32_t smem_u32(const void* p) {
    uint32_t a;
    asm("{ .reg .u64 t; cvta.to.shared.u64 t, %1; cvt.u32.u64 %0, t; }"
        : "=r"(a) : "l"(p));
    return a;
}
__device__ __forceinline__ void cp16(uint32_t dst, const void* src) {
    asm volatile("cp.async.cg.shared.global [%0], [%1], 16;" :: "r"(dst), "l"(src));
}
#define CP_COMMIT() asm volatile("cp.async.commit_group;" ::: "memory")

__device__ __forceinline__ void ldsm4(uint32_t& r0, uint32_t& r1,
                                      uint32_t& r2, uint32_t& r3, uint32_t a) {
    asm volatile("ldmatrix.sync.aligned.m8n8.x4.shared.b16 {%0,%1,%2,%3}, [%4];"
                 : "=r"(r0), "=r"(r1), "=r"(r2), "=r"(r3) : "r"(a));
}
__device__ __forceinline__ void ldsm4t(uint32_t& r0, uint32_t& r1,
                                       uint32_t& r2, uint32_t& r3, uint32_t a) {
    asm volatile("ldmatrix.sync.aligned.m8n8.x4.trans.shared.b16 {%0,%1,%2,%3}, [%4];"
                 : "=r"(r0), "=r"(r1), "=r"(r2), "=r"(r3) : "r"(a));
}
__device__ __forceinline__ void mma16816(float* d, const uint32_t* a,
                                         uint32_t b0, uint32_t b1) {
    asm volatile(
        "mma.sync.aligned.m16n8k16.row.col.f32.bf16.bf16.f32 "
        "{%0,%1,%2,%3}, {%4,%5,%6,%7}, {%8,%9}, {%0,%1,%2,%3};"
        : "+f"(d[0]), "+f"(d[1]), "+f"(d[2]), "+f"(d[3])
        : "r"(a[0]), "r"(a[1]), "r"(a[2]), "r"(a[3]), "r"(b0), "r"(b1));
}
__device__ __forceinline__ uint32_t packbf2(__nv_bfloat16 x, __nv_bfloat16 y) {
    __nv_bfloat162 t(x, y);
    return *(uint32_t*)&t;
}

// ---------------------------------------------------------------------------
// HMMA bf16 hi/lo GEMM (unchanged from round 3; known-good)
// ---------------------------------------------------------------------------
#define ST_AHI  0
#define ST_ALO  10240
#define ST_BHI  20480
#define ST_BLO  30720
#define STAGE_B 40960
#define GK_SMEM_DYN (2 * STAGE_B)   // 80 KB

__global__ __launch_bounds__(256, 1)
void gemm_hilo_kernel(const __nv_bfloat16* __restrict__ Ahi,
                      const __nv_bfloat16* __restrict__ Alo,
                      const __nv_bfloat16* __restrict__ Bhi,
                      const __nv_bfloat16* __restrict__ Blo,
                      float* __restrict__ Cout,
                      __nv_bfloat16* __restrict__ Chi,
                      __nv_bfloat16* __restrict__ Clo,
                      int M, int N, int K)
{
    extern __shared__ char dsm[];
    const uint32_t sbase = smem_u32(dsm);
    const int tid = threadIdx.x, lane = tid & 31, wid = tid >> 5;
    const int wm = wid & 3, wn = wid >> 2;
    const int m0 = blockIdx.y * 128, n0 = blockIdx.x * 128;

    const __nv_bfloat16* gAh = Ahi + (size_t)m0 * K;
    const __nv_bfloat16* gAl = Alo + (size_t)m0 * K;
    const __nv_bfloat16* gBh = Bhi + (size_t)n0 * K;
    const __nv_bfloat16* gBl = Blo + (size_t)n0 * K;

    const int lrow = tid >> 1;
    const int lc0  = (tid & 1) * 2;

    float acc[2][8][4];
#pragma unroll
    for (int mt = 0; mt < 2; mt++)
#pragma unroll
        for (int nt = 0; nt < 8; nt++)
#pragma unroll
            for (int r = 0; r < 4; r++) acc[mt][nt][r] = 0.f;

    const int nk = K >> 5;

    auto load_stage = [&](int buf, int kc) {
        const uint32_t st = sbase + buf * STAGE_B;
        const size_t koff = (size_t)kc * 32;
#pragma unroll
        for (int t = 0; t < 2; t++) {
            const int c16 = lc0 + t;
            const uint32_t doff = lrow * 80 + c16 * 16;
            const size_t soff = (size_t)lrow * K + koff + c16 * 8;
            cp16(st + ST_AHI + doff, gAh + soff);
            cp16(st + ST_ALO + doff, gAl + soff);
            cp16(st + ST_BHI + doff, gBh + soff);
            cp16(st + ST_BLO + doff, gBl + soff);
        }
        CP_COMMIT();
    };

    load_stage(0, 0);

    for (int k = 0; k < nk; k++) {
        if (k + 1 < nk) {
            load_stage((k + 1) & 1, k + 1);
            asm volatile("cp.async.wait_group 1;" ::: "memory");
        } else {
            asm volatile("cp.async.wait_group 0;" ::: "memory");
        }
        __syncthreads();

        const uint32_t st = sbase + (k & 1) * STAGE_B;
#pragma unroll
        for (int ks = 0; ks < 2; ks++) {
            uint32_t ah[2][4], al[2][4];
#pragma unroll
            for (int mt = 0; mt < 2; mt++) {
                const int row = wm * 32 + mt * 16 + (lane & 15);
                const uint32_t off = row * 80 + ks * 32 + ((lane >> 4) << 4);
                ldsm4(ah[mt][0], ah[mt][1], ah[mt][2], ah[mt][3],
                      st + ST_AHI + off);
                ldsm4(al[mt][0], al[mt][1], al[mt][2], al[mt][3],
                      st + ST_ALO + off);
            }
#pragma unroll
            for (int bp = 0; bp < 4; bp++) {
                const int rn = wn * 64 + bp * 16 + ((lane >> 4) << 3) + (lane & 7);
                const uint32_t off = rn * 80 + ks * 32 + (((lane >> 3) & 1) << 4);
                uint32_t bh[4], bl[4];
                ldsm4(bh[0], bh[1], bh[2], bh[3], st + ST_BHI + off);
                ldsm4(bl[0], bl[1], bl[2], bl[3], st + ST_BLO + off);
#pragma unroll
                for (int mt = 0; mt < 2; mt++) {
#pragma unroll
                    for (int h = 0; h < 2; h++) {
                        float* d = acc[mt][2 * bp + h];
                        mma16816(d, ah[mt], bh[2 * h], bh[2 * h + 1]);
                        mma16816(d, ah[mt], bl[2 * h], bl[2 * h + 1]);
                        mma16816(d, al[mt], bh[2 * h], bh[2 * h + 1]);
                    }
                }
            }
        }
        __syncthreads();
    }

    const int lr = lane >> 2, lc = (lane & 3) * 2;
    const int rbase = m0 + wm * 32, cbase = n0 + wn * 64;
    if (Cout) {
#pragma unroll
        for (int mt = 0; mt < 2; mt++) {
#pragma unroll
            for (int nt = 0; nt < 8; nt++) {
                float* d = acc[mt][nt];
                const size_t r0 = (size_t)(rbase + mt * 16 + lr) * N
                                  + cbase + nt * 8 + lc;
                *(float2*)(Cout + r0)         = make_float2(d[0], d[1]);
                *(float2*)(Cout + r0 + 8 * N) = make_float2(d[2], d[3]);
            }
        }
    } else {
#pragma unroll
        for (int mt = 0; mt < 2; mt++) {
#pragma unroll
            for (int nt = 0; nt < 8; nt++) {
                float* d = acc[mt][nt];
#pragma unroll
                for (int half = 0; half < 2; half++) {
                    float v0 = d[half * 2], v1 = d[half * 2 + 1];
                    __nv_bfloat16 h0 = __float2bfloat16(v0);
                    __nv_bfloat16 h1 = __float2bfloat16(v1);
                    __nv_bfloat16 l0 = __float2bfloat16(v0 - __bfloat162float(h0));
                    __nv_bfloat16 l1 = __float2bfloat16(v1 - __bfloat162float(h1));
                    const size_t o = (size_t)(rbase + mt * 16 + lr + half * 8) * N
                                     + cbase + nt * 8 + lc;
                    *(__nv_bfloat162*)(Chi + o) = __nv_bfloat162(h0, h1);
                    *(__nv_bfloat162*)(Clo + o) = __nv_bfloat162(l0, l1);
                }
            }
        }
    }
}

// ---------------------------------------------------------------------------
// fp32 -> bf16 hi/lo elementwise (for x)
// ---------------------------------------------------------------------------
__global__ void convert_hilo_kernel(const float* __restrict__ in,
                                    __nv_bfloat16* __restrict__ hi,
                                    __nv_bfloat16* __restrict__ lo, int n)
{
    int i = blockIdx.x * blockDim.x + threadIdx.x;
    if (i >= n) return;
    float v = in[i];
    __nv_bfloat16 h = __float2bfloat16(v);
    hi[i] = h;
    lo[i] = __float2bfloat16(v - __bfloat162float(h));
}

// ---------------------------------------------------------------------------
// W [Kd,Nd] fp32 -> Wt hi/lo [Nd,Kd] bf16 (tiled transpose)
// ---------------------------------------------------------------------------
__global__ void transpose_hilo_kernel(const float* __restrict__ W,
                                      __nv_bfloat16* __restrict__ hi,
                                      __nv_bfloat16* __restrict__ lo,
                                      int Kd, int Nd)
{
    __shared__ float t[32][33];
    const int tx = threadIdx.x, ty = threadIdx.y;
    const int k0 = blockIdx.y * 32, n0 = blockIdx.x * 32;
#pragma unroll
    for (int i = 0; i < 4; i++)
        t[ty + i * 8][tx] = W[(size_t)(k0 + ty + i * 8) * Nd + n0 + tx];
    __syncthreads();
#pragma unroll
    for (int i = 0; i < 4; i++) {
        float v = t[tx][ty + i * 8];
        __nv_bfloat16 h = __float2bfloat16(v);
        size_t o = (size_t)(n0 + ty + i * 8) * Kd + k0 + tx;
        hi[o] = h;
        lo[o] = __float2bfloat16(v - __bfloat162float(h));
    }
}

// ---------------------------------------------------------------------------
// RoPE on fp32 Q,K -> bf16 hi/lo outputs (fused rope + split)
// ---------------------------------------------------------------------------
__global__ void rope_convert_kernel(const float* __restrict__ Q,
                                    const float* __restrict__ K,
                                    const float* __restrict__ freqs,
                                    __nv_bfloat16* __restrict__ qhi,
                                    __nv_bfloat16* __restrict__ qlo,
                                    __nv_bfloat16* __restrict__ khi,
                                    __nv_bfloat16* __restrict__ klo)
{
    const int total = BATCH * S_LEN * NH * (HD / 2);
    int idx = blockIdx.x * blockDim.x + threadIdx.x;
    if (idx >= total) return;
    int p = idx & 63;
    int s = (idx >> 10) & (S_LEN - 1);
    float f = freqs[s * (HD / 2) + p];
    float sn, cs;
    sincosf(f, &sn, &cs);

    const float2 q = ((const float2*)Q)[idx];
    const float2 k = ((const float2*)K)[idx];
    float q0 = q.x * cs - q.y * sn, q1 = q.x * sn + q.y * cs;
    float k0 = k.x * cs - k.y * sn, k1 = k.x * sn + k.y * cs;

    __nv_bfloat16 qh0 = __float2bfloat16(q0), qh1 = __float2bfloat16(q1);
    __nv_bfloat16 kh0 = __float2bfloat16(k0), kh1 = __float2bfloat16(k1);
    ((__nv_bfloat162*)qhi)[idx] = __nv_bfloat162(qh0, qh1);
    ((__nv_bfloat162*)qlo)[idx] = __nv_bfloat162(
        __float2bfloat16(q0 - __bfloat162float(qh0)),
        __float2bfloat16(q1 - __bfloat162float(qh1)));
    ((__nv_bfloat162*)khi)[idx] = __nv_bfloat162(kh0, kh1);
    ((__nv_bfloat162*)klo)[idx] = __nv_bfloat162(
        __float2bfloat16(k0 - __bfloat162float(kh0)),
        __float2bfloat16(k1 - __bfloat162float(kh1)));
}

// ---------------------------------------------------------------------------
// HMMA causal flash attention, bf16 hi/lo (3-term QK and PV), fp32 softmax.
// BR=BC=64, 128 threads (4 warps x 16 q-rows). Single-buffered K/V smem.
// Row pitch 136 elems (272B) -> conflict-free ldmatrix.
// Writes O directly as bf16 hi/lo for the Wo GEMM.
// ---------------------------------------------------------------------------
#define FP   136            // smem row pitch (elements)
#define FPB  272            // pitch bytes
#define FT   17408          // one 64xHD tile: 64*272 bytes
#define SQHI 0
#define SQLO 17408
#define SKHI 34816
#define SKLO 52224
#define SVHI 69632
#define SVLO 87040
#define FL_SMEM 104448

__global__ __launch_bounds__(128)
void flash_hmma_kernel(const __nv_bfloat16* __restrict__ Qhi,
                       const __nv_bfloat16* __restrict__ Qlo,
                       const __nv_bfloat16* __restrict__ Khi,
                       const __nv_bfloat16* __restrict__ Klo,
                       const __nv_bfloat16* __restrict__ Vhi,
                       const __nv_bfloat16* __restrict__ Vlo,
                       __nv_bfloat16* __restrict__ Ohi,
                       __nv_bfloat16* __restrict__ Olo)
{
    extern __shared__ char dsm[];
    const uint32_t sb = smem_u32(dsm);

    const int tid = threadIdx.x, lane = tid & 31, wm = tid >> 5;
    const int lr = lane >> 2, lc2 = (lane & 3) * 2;

    const int bh = blockIdx.y;
    const int b = bh >> 4, head = bh & 15;
    const int qi = gridDim.x - 1 - blockIdx.x;       // heavy blocks first
    const int q0 = qi * 64;
    const size_t base = ((size_t)b * S_LEN) * D_DIM + head * HD;

    // ---- load Q tile (hi+lo) ----
#pragma unroll
    for (int j = 0; j < 8; j++) {
        int lin = j * 128 + tid;
        int row = lin >> 4, c16 = lin & 15;
        const size_t so = base + (size_t)(q0 + row) * D_DIM + c16 * 8;
        const uint32_t doff = row * FPB + c16 * 16;
        cp16(sb + SQHI + doff, Qhi + so);
        cp16(sb + SQLO + doff, Qlo + so);
    }
    CP_COMMIT();

    float m[2] = {-1e30f, -1e30f}, l[2] = {0.f, 0.f};
    float accO[16][4];
#pragma unroll
    for (int nt = 0; nt < 16; nt++)
#pragma unroll
        for (int e = 0; e < 4; e++) accO[nt][e] = 0.f;

    const float scale = 0.08838834764831845f;
    const int qrow_base = q0 + wm * 16;

    for (int kt = 0; kt <= qi; kt++) {
        const int k0g = kt * 64;
        __syncthreads();
        // ---- load K/V tiles (hi+lo) ----
#pragma unroll
        for (int j = 0; j < 8; j++) {
            int lin = j * 128 + tid;
            int row = lin >> 4, c16 = lin & 15;
            const size_t so = base + (size_t)(k0g + row) * D_DIM + c16 * 8;
            const uint32_t doff = row * FPB + c16 * 16;
            cp16(sb + SKHI + doff, Khi + so);
            cp16(sb + SKLO + doff, Klo + so);
            cp16(sb + SVHI + doff, Vhi + so);
            cp16(sb + SVLO + doff, Vlo + so);
        }
        CP_COMMIT();
        asm volatile("cp.async.wait_group 0;" ::: "memory");
        __syncthreads();

        // ---- S = Q K^T (3-term hi/lo) ----
        float accS[8][4];
#pragma unroll
        for (int n = 0; n < 8; n++)
#pragma unroll
            for (int e = 0; e < 4; e++) accS[n][e] = 0.f;

#pragma unroll
        for (int ks = 0; ks < 8; ks++) {
            const int kk = ks * 16;
            uint32_t qh[4], ql[4];
            const uint32_t qoff = (wm * 16 + (lane & 15)) * FPB
                                  + (kk + ((lane >> 4) << 3)) * 2;
            ldsm4(qh[0], qh[1], qh[2], qh[3], sb + SQHI + qoff);
            ldsm4(ql[0], ql[1], ql[2], ql[3], sb + SQLO + qoff);
#pragma unroll
            for (int np = 0; np < 4; np++) {
                const uint32_t koff =
                    (np * 16 + (lane & 7) + ((lane >> 4) << 3)) * FPB
                    + (kk + (((lane >> 3) & 1) << 3)) * 2;
                uint32_t bh[4], bl[4];
                ldsm4(bh[0], bh[1], bh[2], bh[3], sb + SKHI + koff);
                ldsm4(bl[0], bl[1], bl[2], bl[3], sb + SKLO + koff);
#pragma unroll
                for (int t = 0; t < 2; t++) {
                    float* d = accS[np * 2 + t];
                    mma16816(d, qh, bh[2 * t], bh[2 * t + 1]);
                    mma16816(d, qh, bl[2 * t], bl[2 * t + 1]);
                    mma16816(d, ql, bh[2 * t], bh[2 * t + 1]);
                }
            }
        }

        // ---- scale + causal mask ----
        const bool diag = (kt == qi);
#pragma unroll
        for (int n = 0; n < 8; n++) {
#pragma unroll
            for (int e = 0; e < 4; e++) {
                float v = accS[n][e] * scale;
                if (diag) {
                    int row = qrow_base + lr + 8 * (e >> 1);
                    int col = k0g + n * 8 + lc2 + (e & 1);
                    if (col > row) v = -1e30f;
                }
                accS[n][e] = v;
            }
        }

        // ---- online softmax (per row half h) ----
#pragma unroll
        for (int h = 0; h < 2; h++) {
            float mt = -1e30f;
#pragma unroll
            for (int n = 0; n < 8; n++)
                mt = fmaxf(mt, fmaxf(accS[n][2 * h], accS[n][2 * h + 1]));
            mt = fmaxf(mt, __shfl_xor_sync(0xffffffffu, mt, 1));
            mt = fmaxf(mt, __shfl_xor_sync(0xffffffffu, mt, 2));
            float mn = fmaxf(m[h], mt);
            float alpha = __expf(m[h] - mn);
            m[h] = mn;
            float lt = 0.f;
#pragma unroll
            for (int n = 0; n < 8; n++) {
                float p0 = __expf(accS[n][2 * h] - mn);
                float p1 = __expf(accS[n][2 * h + 1] - mn);
                accS[n][2 * h] = p0;
                accS[n][2 * h + 1] = p1;
                lt += p0 + p1;
            }
            lt += __shfl_xor_sync(0xffffffffu, lt, 1);
            lt += __shfl_xor_sync(0xffffffffu, lt, 2);
            l[h] = l[h] * alpha + lt;
#pragma unroll
            for (int nt = 0; nt < 16; nt++) {
                accO[nt][2 * h] *= alpha;
                accO[nt][2 * h + 1] *= alpha;
            }
        }

        // ---- O += P V (3-term hi/lo) ----
#pragma unroll
        for (int t = 0; t < 4; t++) {          // k-steps over BC (16 each)
            uint32_t phi[4], plo[4];
#pragma unroll
            for (int half = 0; half < 2; half++) {   // acc tiles 2t, 2t+1
                float* s = accS[2 * t + half];
#pragma unroll
                for (int rh = 0; rh < 2; rh++) {     // a0/a1 (rows lr / lr+8)
                    float v0 = s[2 * rh], v1 = s[2 * rh + 1];
                    __nv_bfloat16 h0 = __float2bfloat16(v0);
                    __nv_bfloat16 h1 = __float2bfloat16(v1);
                    phi[half * 2 + rh] = packbf2(h0, h1);
                    plo[half * 2 + rh] = packbf2(
                        __float2bfloat16(v0 - __bfloat162float(h0)),
                        __float2bfloat16(v1 - __bfloat162float(h1)));
                }
            }
            const int kk = t * 16;
#pragma unroll
            for (int np = 0; np < 8; np++) {
                const uint32_t voff = (kk + (lane & 15)) * FPB
                                      + (np * 16 + ((lane >> 4) << 3)) * 2;
                uint32_t vh[4], vl[4];
                ldsm4t(vh[0], vh[1], vh[2], vh[3], sb + SVHI + voff);
                ldsm4t(vl[0], vl[1], vl[2], vl[3], sb + SVLO + voff);
#pragma unroll
                for (int u = 0; u < 2; u++) {
                    float* d = accO[np * 2 + u];
                    mma16816(d, phi, vh[2 * u], vh[2 * u + 1]);
                    mma16816(d, phi, vl[2 * u], vl[2 * u + 1]);
                    mma16816(d, plo, vh[2 * u], vh[2 * u + 1]);
                }
            }
        }
    }

    // ---- epilogue: O/l -> bf16 hi/lo global ----
    const float inv0 = 1.0f / l[0], inv1 = 1.0f / l[1];
#pragma unroll
    for (int nt = 0; nt < 16; nt++) {
#pragma unroll
        for (int h = 0; h < 2; h++) {
            float inv = h ? inv1 : inv0;
            float v0 = accO[nt][2 * h] * inv;
            float v1 = accO[nt][2 * h + 1] * inv;
            __nv_bfloat16 h0 = __float2bfloat16(v0);
            __nv_bfloat16 h1 = __float2bfloat16(v1);
            const size_t o = base
                + (size_t)(qrow_base + lr + 8 * h) * D_DIM + nt * 8 + lc2;
            *(uint32_t*)(Ohi + o) = packbf2(h0, h1);
            *(uint32_t*)(Olo + o) = packbf2(
                __float2bfloat16(v0 - __bfloat162float(h0)),
                __float2bfloat16(v1 - __bfloat162float(h1)));
        }
    }
}

// ---------------------------------------------------------------------------
// Launch
// Inputs: x, freqs, mask(unused: exactly causal), Wq, Wdown, Wkup, Wvup, Wo
// ---------------------------------------------------------------------------
extern "C" void kernel_launch(void* const* d_in, const int* in_sizes, int n_in,
                              void* d_out, int out_size)
{
    const float* x     = (const float*)d_in[0];
    const float* freqs = (const float*)d_in[1];
    const float* Wq    = (const float*)d_in[3];
    const float* Wdn   = (const float*)d_in[4];
    const float* Wku   = (const float*)d_in[5];
    const float* Wvu   = (const float*)d_in[6];
    const float* Wo    = (const float*)d_in[7];
    float* out = (float*)d_out;

    float *Qb, *Kb;
    __nv_bfloat16 *xhi, *xlo, *chi, *clo, *wthi, *wtlo;
    __nv_bfloat16 *qhi, *qlo, *khi, *klo, *vhi, *vlo, *ohi, *olo;
    cudaGetSymbolAddress((void**)&Qb, g_Q);
    cudaGetSymbolAddress((void**)&Kb, g_K);
    cudaGetSymbolAddress((void**)&xhi, g_xhi);
    cudaGetSymbolAddress((void**)&xlo, g_xlo);
    cudaGetSymbolAddress((void**)&chi, g_chi);
    cudaGetSymbolAddress((void**)&clo, g_clo);
    cudaGetSymbolAddress((void**)&qhi, g_qhi);
    cudaGetSymbolAddress((void**)&qlo, g_qlo);
    cudaGetSymbolAddress((void**)&khi, g_khi);
    cudaGetSymbolAddress((void**)&klo, g_klo);
    cudaGetSymbolAddress((void**)&vhi, g_vhi);
    cudaGetSymbolAddress((void**)&vlo, g_vlo);
    cudaGetSymbolAddress((void**)&ohi, g_ohi);
    cudaGetSymbolAddress((void**)&olo, g_olo);
    cudaGetSymbolAddress((void**)&wthi, g_wthi);
    cudaGetSymbolAddress((void**)&wtlo, g_wtlo);

    cudaFuncSetAttribute(gemm_hilo_kernel,
                         cudaFuncAttributeMaxDynamicSharedMemorySize, GK_SMEM_DYN);
    cudaFuncSetAttribute(flash_hmma_kernel,
                         cudaFuncAttributeMaxDynamicSharedMemorySize, FL_SMEM);

    // Weight transposes + x conversion (bandwidth-bound)
    dim3 tb(32, 8);
    transpose_hilo_kernel<<<dim3(64, 64), tb>>>(Wq,  wthi + OFF_WQ,  wtlo + OFF_WQ,  2048, 2048);
    transpose_hilo_kernel<<<dim3(16, 64), tb>>>(Wdn, wthi + OFF_WDN, wtlo + OFF_WDN, 2048, 512);
    transpose_hilo_kernel<<<dim3(64, 16), tb>>>(Wku, wthi + OFF_WKU, wtlo + OFF_WKU, 512, 2048);
    transpose_hilo_kernel<<<dim3(64, 16), tb>>>(Wvu, wthi + OFF_WVU, wtlo + OFF_WVU, 512, 2048);
    transpose_hilo_kernel<<<dim3(64, 64), tb>>>(Wo,  wthi + OFF_WO,  wtlo + OFF_WO,  2048, 2048);

    const int nx = ROWS_TOT * D_DIM;
    convert_hilo_kernel<<<nx / 256, 256>>>(x, xhi, xlo, nx);

    // Projections (HMMA bf16 hi/lo, fp32 accum)
    gemm_hilo_kernel<<<dim3(16, 32), 256, GK_SMEM_DYN>>>(
        xhi, xlo, wthi + OFF_WQ, wtlo + OFF_WQ, Qb, nullptr, nullptr,
        ROWS_TOT, D_DIM, D_DIM);
    gemm_hilo_kernel<<<dim3(4, 32), 256, GK_SMEM_DYN>>>(
        xhi, xlo, wthi + OFF_WDN, wtlo + OFF_WDN, nullptr, chi, clo,
        ROWS_TOT, LAT, D_DIM);
    gemm_hilo_kernel<<<dim3(16, 32), 256, GK_SMEM_DYN>>>(
        chi, clo, wthi + OFF_WKU, wtlo + OFF_WKU, Kb, nullptr, nullptr,
        ROWS_TOT, D_DIM, LAT);
    gemm_hilo_kernel<<<dim3(16, 32), 256, GK_SMEM_DYN>>>(
        chi, clo, wthi + OFF_WVU, wtlo + OFF_WVU, nullptr, vhi, vlo,
        ROWS_TOT, D_DIM, LAT);

    // RoPE + bf16 hi/lo split for Q,K
    const int pairs = BATCH * S_LEN * NH * (HD / 2);
    rope_convert_kernel<<<(pairs + 255) / 256, 256>>>(
        Qb, Kb, freqs, qhi, qlo, khi, klo);

    // Flash attention (causal, HMMA hi/lo) -> O as bf16 hi/lo
    flash_hmma_kernel<<<dim3(S_LEN / 64, BATCH * NH), 128, FL_SMEM>>>(
        qhi, qlo, khi, klo, vhi, vlo, ohi, olo);

    // Output projection
    gemm_hilo_kernel<<<dim3(16, 32), 256, GK_SMEM_DYN>>>(
        ohi, olo, wthi + OFF_WO, wtlo + OFF_WO, out, nullptr, nullptr,
        ROWS_TOT, D_DIM, D_DIM);
}

// round 5
// speedup vs baseline: 2.9491x; 1.0323x over previous
#include <cuda_runtime.h>
#include <cuda_bf16.h>
#include <cstdint>
#include <math.h>

// Problem constants
#define BATCH   2
#define S_LEN   2048
#define D_DIM   2048
#define NH      16
#define HD      128
#define LAT     512
#define ROWS_TOT (BATCH * S_LEN)   // 4096

// ---------------------------------------------------------------------------
// Scratch (__device__ globals; allocation-free rule)
// ---------------------------------------------------------------------------
__device__ float g_Q[ROWS_TOT * D_DIM];   // fp32 Q after proj (pre-rope)
__device__ float g_K[ROWS_TOT * D_DIM];   // fp32 K after proj (pre-rope)

__device__ __nv_bfloat16 g_xhi[ROWS_TOT * D_DIM];
__device__ __nv_bfloat16 g_xlo[ROWS_TOT * D_DIM];
__device__ __nv_bfloat16 g_chi[ROWS_TOT * LAT];
__device__ __nv_bfloat16 g_clo[ROWS_TOT * LAT];
__device__ __nv_bfloat16 g_qhi[ROWS_TOT * D_DIM];
__device__ __nv_bfloat16 g_qlo[ROWS_TOT * D_DIM];
__device__ __nv_bfloat16 g_khi[ROWS_TOT * D_DIM];
__device__ __nv_bfloat16 g_klo[ROWS_TOT * D_DIM];
__device__ __nv_bfloat16 g_vhi[ROWS_TOT * D_DIM];
__device__ __nv_bfloat16 g_vlo[ROWS_TOT * D_DIM];
__device__ __nv_bfloat16 g_ohi[ROWS_TOT * D_DIM];
__device__ __nv_bfloat16 g_olo[ROWS_TOT * D_DIM];

// Transposed-weight pool ([N,K] K-major bf16), hi and lo parts.
#define OFF_WQ  0
#define OFF_WDN 4194304
#define OFF_WKU 5242880
#define OFF_WVU 6291456
#define OFF_WO  7340032
#define WT_TOTAL 11534336
__device__ __nv_bfloat16 g_wthi[WT_TOTAL];
__device__ __nv_bfloat16 g_wtlo[WT_TOTAL];

// ---------------------------------------------------------------------------
// PTX helpers (sm_80+ features only — harness targets plain sm_103)
// ---------------------------------------------------------------------------
__device__ __forceinline__ uint32_t smem_u32(const void* p) {
    uint32_t a;
    asm("{ .reg .u64 t; cvta.to.shared.u64 t, %1; cvt.u32.u64 %0, t; }"
        : "=r"(a) : "l"(p));
    return a;
}
__device__ __forceinline__ void cp16(uint32_t dst, const void* src) {
    asm volatile("cp.async.cg.shared.global [%0], [%1], 16;" :: "r"(dst), "l"(src));
}
#define CP_COMMIT() asm volatile("cp.async.commit_group;" ::: "memory")

__device__ __forceinline__ void ldsm4(uint32_t& r0, uint32_t& r1,
                                      uint32_t& r2, uint32_t& r3, uint32_t a) {
    asm volatile("ldmatrix.sync.aligned.m8n8.x4.shared.b16 {%0,%1,%2,%3}, [%4];"
                 : "=r"(r0), "=r"(r1), "=r"(r2), "=r"(r3) : "r"(a));
}
__device__ __forceinline__ void ldsm4t(uint32_t& r0, uint32_t& r1,
                                       uint32_t& r2, uint32_t& r3, uint32_t a) {
    asm volatile("ldmatrix.sync.aligned.m8n8.x4.trans.shared.b16 {%0,%1,%2,%3}, [%4];"
                 : "=r"(r0), "=r"(r1), "=r"(r2), "=r"(r3) : "r"(a));
}
__device__ __forceinline__ void mma16816(float* d, const uint32_t* a,
                                         uint32_t b0, uint32_t b1) {
    asm volatile(
        "mma.sync.aligned.m16n8k16.row.col.f32.bf16.bf16.f32 "
        "{%0,%1,%2,%3}, {%4,%5,%6,%7}, {%8,%9}, {%0,%1,%2,%3};"
        : "+f"(d[0]), "+f"(d[1]), "+f"(d[2]), "+f"(d[3])
        : "r"(a[0]), "r"(a[1]), "r"(a[2]), "r"(a[3]), "r"(b0), "r"(b1));
}
__device__ __forceinline__ uint32_t packbf2(__nv_bfloat16 x, __nv_bfloat16 y) {
    __nv_bfloat162 t(x, y);
    return *(uint32_t*)&t;
}

// ---------------------------------------------------------------------------
// HMMA bf16 hi/lo GEMM: C[M,N] = A[M,K] @ Bt[N,K]^T, fp32 accumulation.
// 128x128x32 tiles, 256 thr (8 warps, 4x2), 4-stage cp.async multistage
// pipeline (CUTLASS rotation: one __syncthreads per k-iter, load issued
// before compute into the buffer computed last iteration).
// ---------------------------------------------------------------------------
#define ST_AHI  0
#define ST_ALO  10240
#define ST_BHI  20480
#define ST_BLO  30720
#define STAGE_B 40960
#define GK_STAGES 4
#define GK_SMEM_DYN (GK_STAGES * STAGE_B)   // 160 KB

__global__ __launch_bounds__(256, 1)
void gemm_hilo_kernel(const __nv_bfloat16* __restrict__ Ahi,
                      const __nv_bfloat16* __restrict__ Alo,
                      const __nv_bfloat16* __restrict__ Bhi,
                      const __nv_bfloat16* __restrict__ Blo,
                      float* __restrict__ Cout,
                      __nv_bfloat16* __restrict__ Chi,
                      __nv_bfloat16* __restrict__ Clo,
                      int M, int N, int K)
{
    extern __shared__ char dsm[];
    const uint32_t sbase = smem_u32(dsm);
    const int tid = threadIdx.x, lane = tid & 31, wid = tid >> 5;
    const int wm = wid & 3, wn = wid >> 2;
    const int m0 = blockIdx.y * 128, n0 = blockIdx.x * 128;

    const __nv_bfloat16* gAh = Ahi + (size_t)m0 * K;
    const __nv_bfloat16* gAl = Alo + (size_t)m0 * K;
    const __nv_bfloat16* gBh = Bhi + (size_t)n0 * K;
    const __nv_bfloat16* gBl = Blo + (size_t)n0 * K;

    const int lrow = tid >> 1;
    const int lc0  = (tid & 1) * 2;

    float acc[2][8][4];
#pragma unroll
    for (int mt = 0; mt < 2; mt++)
#pragma unroll
        for (int nt = 0; nt < 8; nt++)
#pragma unroll
            for (int r = 0; r < 4; r++) acc[mt][nt][r] = 0.f;

    const int nk = K >> 5;

    auto load_stage = [&](int buf, int kc) {
        const uint32_t st = sbase + buf * STAGE_B;
        const size_t koff = (size_t)kc * 32;
#pragma unroll
        for (int t = 0; t < 2; t++) {
            const int c16 = lc0 + t;
            const uint32_t doff = lrow * 80 + c16 * 16;
            const size_t soff = (size_t)lrow * K + koff + c16 * 8;
            cp16(st + ST_AHI + doff, gAh + soff);
            cp16(st + ST_ALO + doff, gAl + soff);
            cp16(st + ST_BHI + doff, gBh + soff);
            cp16(st + ST_BLO + doff, gBl + soff);
        }
        CP_COMMIT();
    };

    // Prologue: issue GK_STAGES-1 stages
#pragma unroll
    for (int p = 0; p < GK_STAGES - 1; p++) load_stage(p, p);

    for (int k = 0; k < nk; k++) {
        // Stage k complete when at most GK_STAGES-2 groups still pending.
        asm volatile("cp.async.wait_group %0;" :: "n"(GK_STAGES - 2) : "memory");
        __syncthreads();

        // Issue stage k+GK_STAGES-1 into the buffer computed last iteration
        // (barrier above guarantees every warp finished reading it).
        if (k + GK_STAGES - 1 < nk)
            load_stage((k + GK_STAGES - 1) % GK_STAGES, k + GK_STAGES - 1);

        const uint32_t st = sbase + (k % GK_STAGES) * STAGE_B;
#pragma unroll
        for (int ks = 0; ks < 2; ks++) {
            uint32_t ah[2][4], al[2][4];
#pragma unroll
            for (int mt = 0; mt < 2; mt++) {
                const int row = wm * 32 + mt * 16 + (lane & 15);
                const uint32_t off = row * 80 + ks * 32 + ((lane >> 4) << 4);
                ldsm4(ah[mt][0], ah[mt][1], ah[mt][2], ah[mt][3],
                      st + ST_AHI + off);
                ldsm4(al[mt][0], al[mt][1], al[mt][2], al[mt][3],
                      st + ST_ALO + off);
            }
#pragma unroll
            for (int bp = 0; bp < 4; bp++) {
                const int rn = wn * 64 + bp * 16 + ((lane >> 4) << 3) + (lane & 7);
                const uint32_t off = rn * 80 + ks * 32 + (((lane >> 3) & 1) << 4);
                uint32_t bh[4], bl[4];
                ldsm4(bh[0], bh[1], bh[2], bh[3], st + ST_BHI + off);
                ldsm4(bl[0], bl[1], bl[2], bl[3], st + ST_BLO + off);
#pragma unroll
                for (int mt = 0; mt < 2; mt++) {
#pragma unroll
                    for (int h = 0; h < 2; h++) {
                        float* d = acc[mt][2 * bp + h];
                        mma16816(d, ah[mt], bh[2 * h], bh[2 * h + 1]);
                        mma16816(d, ah[mt], bl[2 * h], bl[2 * h + 1]);
                        mma16816(d, al[mt], bh[2 * h], bh[2 * h + 1]);
                    }
                }
            }
        }
    }

    const int lr = lane >> 2, lc = (lane & 3) * 2;
    const int rbase = m0 + wm * 32, cbase = n0 + wn * 64;
    if (Cout) {
#pragma unroll
        for (int mt = 0; mt < 2; mt++) {
#pragma unroll
            for (int nt = 0; nt < 8; nt++) {
                float* d = acc[mt][nt];
                const size_t r0 = (size_t)(rbase + mt * 16 + lr) * N
                                  + cbase + nt * 8 + lc;
                *(float2*)(Cout + r0)         = make_float2(d[0], d[1]);
                *(float2*)(Cout + r0 + 8 * N) = make_float2(d[2], d[3]);
            }
        }
    } else {
#pragma unroll
        for (int mt = 0; mt < 2; mt++) {
#pragma unroll
            for (int nt = 0; nt < 8; nt++) {
                float* d = acc[mt][nt];
#pragma unroll
                for (int half = 0; half < 2; half++) {
                    float v0 = d[half * 2], v1 = d[half * 2 + 1];
                    __nv_bfloat16 h0 = __float2bfloat16(v0);
                    __nv_bfloat16 h1 = __float2bfloat16(v1);
                    __nv_bfloat16 l0 = __float2bfloat16(v0 - __bfloat162float(h0));
                    __nv_bfloat16 l1 = __float2bfloat16(v1 - __bfloat162float(h1));
                    const size_t o = (size_t)(rbase + mt * 16 + lr + half * 8) * N
                                     + cbase + nt * 8 + lc;
                    *(__nv_bfloat162*)(Chi + o) = __nv_bfloat162(h0, h1);
                    *(__nv_bfloat162*)(Clo + o) = __nv_bfloat162(l0, l1);
                }
            }
        }
    }
}

// ---------------------------------------------------------------------------
// fp32 -> bf16 hi/lo elementwise (for x)
// ---------------------------------------------------------------------------
__global__ void convert_hilo_kernel(const float* __restrict__ in,
                                    __nv_bfloat16* __restrict__ hi,
                                    __nv_bfloat16* __restrict__ lo, int n)
{
    int i = blockIdx.x * blockDim.x + threadIdx.x;
    if (i >= n) return;
    float v = in[i];
    __nv_bfloat16 h = __float2bfloat16(v);
    hi[i] = h;
    lo[i] = __float2bfloat16(v - __bfloat162float(h));
}

// ---------------------------------------------------------------------------
// W [Kd,Nd] fp32 -> Wt hi/lo [Nd,Kd] bf16 (tiled transpose)
// ---------------------------------------------------------------------------
__global__ void transpose_hilo_kernel(const float* __restrict__ W,
                                      __nv_bfloat16* __restrict__ hi,
                                      __nv_bfloat16* __restrict__ lo,
                                      int Kd, int Nd)
{
    __shared__ float t[32][33];
    const int tx = threadIdx.x, ty = threadIdx.y;
    const int k0 = blockIdx.y * 32, n0 = blockIdx.x * 32;
#pragma unroll
    for (int i = 0; i < 4; i++)
        t[ty + i * 8][tx] = W[(size_t)(k0 + ty + i * 8) * Nd + n0 + tx];
    __syncthreads();
#pragma unroll
    for (int i = 0; i < 4; i++) {
        float v = t[tx][ty + i * 8];
        __nv_bfloat16 h = __float2bfloat16(v);
        size_t o = (size_t)(n0 + ty + i * 8) * Kd + k0 + tx;
        hi[o] = h;
        lo[o] = __float2bfloat16(v - __bfloat162float(h));
    }
}

// ---------------------------------------------------------------------------
// RoPE on fp32 Q,K -> bf16 hi/lo outputs (fused rope + split)
// ---------------------------------------------------------------------------
__global__ void rope_convert_kernel(const float* __restrict__ Q,
                                    const float* __restrict__ K,
                                    const float* __restrict__ freqs,
                                    __nv_bfloat16* __restrict__ qhi,
                                    __nv_bfloat16* __restrict__ qlo,
                                    __nv_bfloat16* __restrict__ khi,
                                    __nv_bfloat16* __restrict__ klo)
{
    const int total = BATCH * S_LEN * NH * (HD / 2);
    int idx = blockIdx.x * blockDim.x + threadIdx.x;
    if (idx >= total) return;
    int p = idx & 63;
    int s = (idx >> 10) & (S_LEN - 1);
    float f = freqs[s * (HD / 2) + p];
    float sn, cs;
    sincosf(f, &sn, &cs);

    const float2 q = ((const float2*)Q)[idx];
    const float2 k = ((const float2*)K)[idx];
    float q0 = q.x * cs - q.y * sn, q1 = q.x * sn + q.y * cs;
    float k0 = k.x * cs - k.y * sn, k1 = k.x * sn + k.y * cs;

    __nv_bfloat16 qh0 = __float2bfloat16(q0), qh1 = __float2bfloat16(q1);
    __nv_bfloat16 kh0 = __float2bfloat16(k0), kh1 = __float2bfloat16(k1);
    ((__nv_bfloat162*)qhi)[idx] = __nv_bfloat162(qh0, qh1);
    ((__nv_bfloat162*)qlo)[idx] = __nv_bfloat162(
        __float2bfloat16(q0 - __bfloat162float(qh0)),
        __float2bfloat16(q1 - __bfloat162float(qh1)));
    ((__nv_bfloat162*)khi)[idx] = __nv_bfloat162(kh0, kh1);
    ((__nv_bfloat162*)klo)[idx] = __nv_bfloat162(
        __float2bfloat16(k0 - __bfloat162float(kh0)),
        __float2bfloat16(k1 - __bfloat162float(kh1)));
}

// ---------------------------------------------------------------------------
// HMMA causal flash attention, bf16 hi/lo (3-term QK and PV), fp32 softmax.
// BR=BC=64, 128 threads (4 warps x 16 q-rows). Single-buffered K/V smem
// (104KB => 2 CTAs/SM for cross-CTA overlap). Unchanged from round 4.
// ---------------------------------------------------------------------------
#define FP   136
#define FPB  272
#define FT   17408
#define SQHI 0
#define SQLO 17408
#define SKHI 34816
#define SKLO 52224
#define SVHI 69632
#define SVLO 87040
#define FL_SMEM 104448

__global__ __launch_bounds__(128)
void flash_hmma_kernel(const __nv_bfloat16* __restrict__ Qhi,
                       const __nv_bfloat16* __restrict__ Qlo,
                       const __nv_bfloat16* __restrict__ Khi,
                       const __nv_bfloat16* __restrict__ Klo,
                       const __nv_bfloat16* __restrict__ Vhi,
                       const __nv_bfloat16* __restrict__ Vlo,
                       __nv_bfloat16* __restrict__ Ohi,
                       __nv_bfloat16* __restrict__ Olo)
{
    extern __shared__ char dsm[];
    const uint32_t sb = smem_u32(dsm);

    const int tid = threadIdx.x, lane = tid & 31, wm = tid >> 5;
    const int lr = lane >> 2, lc2 = (lane & 3) * 2;

    const int bh = blockIdx.y;
    const int b = bh >> 4, head = bh & 15;
    const int qi = gridDim.x - 1 - blockIdx.x;       // heavy blocks first
    const int q0 = qi * 64;
    const size_t base = ((size_t)b * S_LEN) * D_DIM + head * HD;

#pragma unroll
    for (int j = 0; j < 8; j++) {
        int lin = j * 128 + tid;
        int row = lin >> 4, c16 = lin & 15;
        const size_t so = base + (size_t)(q0 + row) * D_DIM + c16 * 8;
        const uint32_t doff = row * FPB + c16 * 16;
        cp16(sb + SQHI + doff, Qhi + so);
        cp16(sb + SQLO + doff, Qlo + so);
    }
    CP_COMMIT();

    float m[2] = {-1e30f, -1e30f}, l[2] = {0.f, 0.f};
    float accO[16][4];
#pragma unroll
    for (int nt = 0; nt < 16; nt++)
#pragma unroll
        for (int e = 0; e < 4; e++) accO[nt][e] = 0.f;

    const float scale = 0.08838834764831845f;
    const int qrow_base = q0 + wm * 16;

    for (int kt = 0; kt <= qi; kt++) {
        const int k0g = kt * 64;
        __syncthreads();
#pragma unroll
        for (int j = 0; j < 8; j++) {
            int lin = j * 128 + tid;
            int row = lin >> 4, c16 = lin & 15;
            const size_t so = base + (size_t)(k0g + row) * D_DIM + c16 * 8;
            const uint32_t doff = row * FPB + c16 * 16;
            cp16(sb + SKHI + doff, Khi + so);
            cp16(sb + SKLO + doff, Klo + so);
            cp16(sb + SVHI + doff, Vhi + so);
            cp16(sb + SVLO + doff, Vlo + so);
        }
        CP_COMMIT();
        asm volatile("cp.async.wait_group 0;" ::: "memory");
        __syncthreads();

        float accS[8][4];
#pragma unroll
        for (int n = 0; n < 8; n++)
#pragma unroll
            for (int e = 0; e < 4; e++) accS[n][e] = 0.f;

#pragma unroll
        for (int ks = 0; ks < 8; ks++) {
            const int kk = ks * 16;
            uint32_t qh[4], ql[4];
            const uint32_t qoff = (wm * 16 + (lane & 15)) * FPB
                                  + (kk + ((lane >> 4) << 3)) * 2;
            ldsm4(qh[0], qh[1], qh[2], qh[3], sb + SQHI + qoff);
            ldsm4(ql[0], ql[1], ql[2], ql[3], sb + SQLO + qoff);
#pragma unroll
            for (int np = 0; np < 4; np++) {
                const uint32_t koff =
                    (np * 16 + (lane & 7) + ((lane >> 4) << 3)) * FPB
                    + (kk + (((lane >> 3) & 1) << 3)) * 2;
                uint32_t bh[4], bl[4];
                ldsm4(bh[0], bh[1], bh[2], bh[3], sb + SKHI + koff);
                ldsm4(bl[0], bl[1], bl[2], bl[3], sb + SKLO + koff);
#pragma unroll
                for (int t = 0; t < 2; t++) {
                    float* d = accS[np * 2 + t];
                    mma16816(d, qh, bh[2 * t], bh[2 * t + 1]);
                    mma16816(d, qh, bl[2 * t], bl[2 * t + 1]);
                    mma16816(d, ql, bh[2 * t], bh[2 * t + 1]);
                }
            }
        }

        const bool diag = (kt == qi);
#pragma unroll
        for (int n = 0; n < 8; n++) {
#pragma unroll
            for (int e = 0; e < 4; e++) {
                float v = accS[n][e] * scale;
                if (diag) {
                    int row = qrow_base + lr + 8 * (e >> 1);
                    int col = k0g + n * 8 + lc2 + (e & 1);
                    if (col > row) v = -1e30f;
                }
                accS[n][e] = v;
            }
        }

#pragma unroll
        for (int h = 0; h < 2; h++) {
            float mt = -1e30f;
#pragma unroll
            for (int n = 0; n < 8; n++)
                mt = fmaxf(mt, fmaxf(accS[n][2 * h], accS[n][2 * h + 1]));
            mt = fmaxf(mt, __shfl_xor_sync(0xffffffffu, mt, 1));
            mt = fmaxf(mt, __shfl_xor_sync(0xffffffffu, mt, 2));
            float mn = fmaxf(m[h], mt);
            float alpha = __expf(m[h] - mn);
            m[h] = mn;
            float lt = 0.f;
#pragma unroll
            for (int n = 0; n < 8; n++) {
                float p0 = __expf(accS[n][2 * h] - mn);
                float p1 = __expf(accS[n][2 * h + 1] - mn);
                accS[n][2 * h] = p0;
                accS[n][2 * h + 1] = p1;
                lt += p0 + p1;
            }
            lt += __shfl_xor_sync(0xffffffffu, lt, 1);
            lt += __shfl_xor_sync(0xffffffffu, lt, 2);
            l[h] = l[h] * alpha + lt;
#pragma unroll
            for (int nt = 0; nt < 16; nt++) {
                accO[nt][2 * h] *= alpha;
                accO[nt][2 * h + 1] *= alpha;
            }
        }

#pragma unroll
        for (int t = 0; t < 4; t++) {
            uint32_t phi[4], plo[4];
#pragma unroll
            for (int half = 0; half < 2; half++) {
                float* s = accS[2 * t + half];
#pragma unroll
                for (int rh = 0; rh < 2; rh++) {
                    float v0 = s[2 * rh], v1 = s[2 * rh + 1];
                    __nv_bfloat16 h0 = __float2bfloat16(v0);
                    __nv_bfloat16 h1 = __float2bfloat16(v1);
                    phi[half * 2 + rh] = packbf2(h0, h1);
                    plo[half * 2 + rh] = packbf2(
                        __float2bfloat16(v0 - __bfloat162float(h0)),
                        __float2bfloat16(v1 - __bfloat162float(h1)));
                }
            }
            const int kk = t * 16;
#pragma unroll
            for (int np = 0; np < 8; np++) {
                const uint32_t voff = (kk + (lane & 15)) * FPB
                                      + (np * 16 + ((lane >> 4) << 3)) * 2;
                uint32_t vh[4], vl[4];
                ldsm4t(vh[0], vh[1], vh[2], vh[3], sb + SVHI + voff);
                ldsm4t(vl[0], vl[1], vl[2], vl[3], sb + SVLO + voff);
#pragma unroll
                for (int u = 0; u < 2; u++) {
                    float* d = accO[np * 2 + u];
                    mma16816(d, phi, vh[2 * u], vh[2 * u + 1]);
                    mma16816(d, phi, vl[2 * u], vl[2 * u + 1]);
                    mma16816(d, plo, vh[2 * u], vh[2 * u + 1]);
                }
            }
        }
    }

    const float inv0 = 1.0f / l[0], inv1 = 1.0f / l[1];
#pragma unroll
    for (int nt = 0; nt < 16; nt++) {
#pragma unroll
        for (int h = 0; h < 2; h++) {
            float inv = h ? inv1 : inv0;
            float v0 = accO[nt][2 * h] * inv;
            float v1 = accO[nt][2 * h + 1] * inv;
            __nv_bfloat16 h0 = __float2bfloat16(v0);
            __nv_bfloat16 h1 = __float2bfloat16(v1);
            const size_t o = base
                + (size_t)(qrow_base + lr + 8 * h) * D_DIM + nt * 8 + lc2;
            *(uint32_t*)(Ohi + o) = packbf2(h0, h1);
            *(uint32_t*)(Olo + o) = packbf2(
                __float2bfloat16(v0 - __bfloat162float(h0)),
                __float2bfloat16(v1 - __bfloat162float(h1)));
        }
    }
}

// ---------------------------------------------------------------------------
// Launch
// Inputs: x, freqs, mask(unused: exactly causal), Wq, Wdown, Wkup, Wvup, Wo
// ---------------------------------------------------------------------------
extern "C" void kernel_launch(void* const* d_in, const int* in_sizes, int n_in,
                              void* d_out, int out_size)
{
    const float* x     = (const float*)d_in[0];
    const float* freqs = (const float*)d_in[1];
    const float* Wq    = (const float*)d_in[3];
    const float* Wdn   = (const float*)d_in[4];
    const float* Wku   = (const float*)d_in[5];
    const float* Wvu   = (const float*)d_in[6];
    const float* Wo    = (const float*)d_in[7];
    float* out = (float*)d_out;

    float *Qb, *Kb;
    __nv_bfloat16 *xhi, *xlo, *chi, *clo, *wthi, *wtlo;
    __nv_bfloat16 *qhi, *qlo, *khi, *klo, *vhi, *vlo, *ohi, *olo;
    cudaGetSymbolAddress((void**)&Qb, g_Q);
    cudaGetSymbolAddress((void**)&Kb, g_K);
    cudaGetSymbolAddress((void**)&xhi, g_xhi);
    cudaGetSymbolAddress((void**)&xlo, g_xlo);
    cudaGetSymbolAddress((void**)&chi, g_chi);
    cudaGetSymbolAddress((void**)&clo, g_clo);
    cudaGetSymbolAddress((void**)&qhi, g_qhi);
    cudaGetSymbolAddress((void**)&qlo, g_qlo);
    cudaGetSymbolAddress((void**)&khi, g_khi);
    cudaGetSymbolAddress((void**)&klo, g_klo);
    cudaGetSymbolAddress((void**)&vhi, g_vhi);
    cudaGetSymbolAddress((void**)&vlo, g_vlo);
    cudaGetSymbolAddress((void**)&ohi, g_ohi);
    cudaGetSymbolAddress((void**)&olo, g_olo);
    cudaGetSymbolAddress((void**)&wthi, g_wthi);
    cudaGetSymbolAddress((void**)&wtlo, g_wtlo);

    cudaFuncSetAttribute(gemm_hilo_kernel,
                         cudaFuncAttributeMaxDynamicSharedMemorySize, GK_SMEM_DYN);
    cudaFuncSetAttribute(flash_hmma_kernel,
                         cudaFuncAttributeMaxDynamicSharedMemorySize, FL_SMEM);

    // Weight transposes + x conversion (bandwidth-bound)
    dim3 tb(32, 8);
    transpose_hilo_kernel<<<dim3(64, 64), tb>>>(Wq,  wthi + OFF_WQ,  wtlo + OFF_WQ,  2048, 2048);
    transpose_hilo_kernel<<<dim3(16, 64), tb>>>(Wdn, wthi + OFF_WDN, wtlo + OFF_WDN, 2048, 512);
    transpose_hilo_kernel<<<dim3(64, 16), tb>>>(Wku, wthi + OFF_WKU, wtlo + OFF_WKU, 512, 2048);
    transpose_hilo_kernel<<<dim3(64, 16), tb>>>(Wvu, wthi + OFF_WVU, wtlo + OFF_WVU, 512, 2048);
    transpose_hilo_kernel<<<dim3(64, 64), tb>>>(Wo,  wthi + OFF_WO,  wtlo + OFF_WO,  2048, 2048);

    const int nx = ROWS_TOT * D_DIM;
    convert_hilo_kernel<<<nx / 256, 256>>>(x, xhi, xlo, nx);

    // Projections (HMMA bf16 hi/lo, fp32 accum)
    gemm_hilo_kernel<<<dim3(16, 32), 256, GK_SMEM_DYN>>>(
        xhi, xlo, wthi + OFF_WQ, wtlo + OFF_WQ, Qb, nullptr, nullptr,
        ROWS_TOT, D_DIM, D_DIM);
    gemm_hilo_kernel<<<dim3(4, 32), 256, GK_SMEM_DYN>>>(
        xhi, xlo, wthi + OFF_WDN, wtlo + OFF_WDN, nullptr, chi, clo,
        ROWS_TOT, LAT, D_DIM);
    gemm_hilo_kernel<<<dim3(16, 32), 256, GK_SMEM_DYN>>>(
        chi, clo, wthi + OFF_WKU, wtlo + OFF_WKU, Kb, nullptr, nullptr,
        ROWS_TOT, D_DIM, LAT);
    gemm_hilo_kernel<<<dim3(16, 32), 256, GK_SMEM_DYN>>>(
        chi, clo, wthi + OFF_WVU, wtlo + OFF_WVU, nullptr, vhi, vlo,
        ROWS_TOT, D_DIM, LAT);

    // RoPE + bf16 hi/lo split for Q,K
    const int pairs = BATCH * S_LEN * NH * (HD / 2);
    rope_convert_kernel<<<(pairs + 255) / 256, 256>>>(
        Qb, Kb, freqs, qhi, qlo, khi, klo);

    // Flash attention (causal, HMMA hi/lo) -> O as bf16 hi/lo
    flash_hmma_kernel<<<dim3(S_LEN / 64, BATCH * NH), 128, FL_SMEM>>>(
        qhi, qlo, khi, klo, vhi, vlo, ohi, olo);

    // Output projection
    gemm_hilo_kernel<<<dim3(16, 32), 256, GK_SMEM_DYN>>>(
        ohi, olo, wthi + OFF_WO, wtlo + OFF_WO, out, nullptr, nullptr,
        ROWS_TOT, D_DIM, D_DIM);
}

// round 6
// speedup vs baseline: 3.2589x; 1.1050x over previous
#include <cuda_runtime.h>
#include <cuda_bf16.h>
#include <cstdint>
#include <math.h>

// Problem constants
#define BATCH   2
#define S_LEN   2048
#define D_DIM   2048
#define NH      16
#define HD      128
#define LAT     512
#define ROWS_TOT (BATCH * S_LEN)   // 4096

// ---------------------------------------------------------------------------
// Scratch (__device__ globals; allocation-free rule)
// ---------------------------------------------------------------------------
__device__ float g_Q[ROWS_TOT * D_DIM];   // fp32 Q after proj (pre-rope)
__device__ float g_K[ROWS_TOT * D_DIM];   // fp32 K after proj (pre-rope)

__device__ __nv_bfloat16 g_xhi[ROWS_TOT * D_DIM];
__device__ __nv_bfloat16 g_xlo[ROWS_TOT * D_DIM];
__device__ __nv_bfloat16 g_chi[ROWS_TOT * LAT];
__device__ __nv_bfloat16 g_clo[ROWS_TOT * LAT];
__device__ __nv_bfloat16 g_qhi[ROWS_TOT * D_DIM];
__device__ __nv_bfloat16 g_qlo[ROWS_TOT * D_DIM];
__device__ __nv_bfloat16 g_khi[ROWS_TOT * D_DIM];
__device__ __nv_bfloat16 g_klo[ROWS_TOT * D_DIM];
__device__ __nv_bfloat16 g_vhi[ROWS_TOT * D_DIM];
__device__ __nv_bfloat16 g_vlo[ROWS_TOT * D_DIM];
__device__ __nv_bfloat16 g_ohi[ROWS_TOT * D_DIM];
__device__ __nv_bfloat16 g_olo[ROWS_TOT * D_DIM];

// Transposed-weight pool ([N,K] K-major bf16), hi and lo parts.
#define OFF_WQ  0
#define OFF_WDN 4194304
#define OFF_WKU 5242880
#define OFF_WVU 6291456
#define OFF_WO  7340032
#define WT_TOTAL 11534336
__device__ __nv_bfloat16 g_wthi[WT_TOTAL];
__device__ __nv_bfloat16 g_wtlo[WT_TOTAL];

// ---------------------------------------------------------------------------
// PTX helpers (sm_80+ features only — harness targets plain sm_103)
// ---------------------------------------------------------------------------
__device__ __forceinline__ uint32_t smem_u32(const void* p) {
    uint32_t a;
    asm("{ .reg .u64 t; cvta.to.shared.u64 t, %1; cvt.u32.u64 %0, t; }"
        : "=r"(a) : "l"(p));
    return a;
}
__device__ __forceinline__ void cp16(uint32_t dst, const void* src) {
    asm volatile("cp.async.cg.shared.global [%0], [%1], 16;" :: "r"(dst), "l"(src));
}
#define CP_COMMIT() asm volatile("cp.async.commit_group;" ::: "memory")

__device__ __forceinline__ void ldsm4(uint32_t& r0, uint32_t& r1,
                                      uint32_t& r2, uint32_t& r3, uint32_t a) {
    asm volatile("ldmatrix.sync.aligned.m8n8.x4.shared.b16 {%0,%1,%2,%3}, [%4];"
                 : "=r"(r0), "=r"(r1), "=r"(r2), "=r"(r3) : "r"(a));
}
__device__ __forceinline__ void ldsm4t(uint32_t& r0, uint32_t& r1,
                                       uint32_t& r2, uint32_t& r3, uint32_t a) {
    asm volatile("ldmatrix.sync.aligned.m8n8.x4.trans.shared.b16 {%0,%1,%2,%3}, [%4];"
                 : "=r"(r0), "=r"(r1), "=r"(r2), "=r"(r3) : "r"(a));
}
// NOTE: non-volatile — pure register op, lets the compiler/ptxas interleave
// MMAs to break accumulator RAW chains.
__device__ __forceinline__ void mma16816(float* d, const uint32_t* a,
                                         uint32_t b0, uint32_t b1) {
    asm("mma.sync.aligned.m16n8k16.row.col.f32.bf16.bf16.f32 "
        "{%0,%1,%2,%3}, {%4,%5,%6,%7}, {%8,%9}, {%0,%1,%2,%3};"
        : "+f"(d[0]), "+f"(d[1]), "+f"(d[2]), "+f"(d[3])
        : "r"(a[0]), "r"(a[1]), "r"(a[2]), "r"(a[3]), "r"(b0), "r"(b1));
}
__device__ __forceinline__ uint32_t packbf2(__nv_bfloat16 x, __nv_bfloat16 y) {
    __nv_bfloat162 t(x, y);
    return *(uint32_t*)&t;
}

// ---------------------------------------------------------------------------
// HMMA bf16 hi/lo GEMM: C[M,N] = A[M,K] @ Bt[N,K]^T, fp32 accumulation.
// 128x128x32 tiles, 256 thr (8 warps, 4x2). 2-stage cp.async ring with the
// single-barrier rotation (80KB smem => 2 CTAs/SM => 4 warps/SMSP for MMA
// latency hiding). MMAs issued term-major so same-accumulator reuse is 4
// independent MMAs apart.
// ---------------------------------------------------------------------------
#define ST_AHI  0
#define ST_ALO  10240
#define ST_BHI  20480
#define ST_BLO  30720
#define STAGE_B 40960
#define GK_SMEM_DYN (2 * STAGE_B)   // 80 KB

__global__ __launch_bounds__(256, 2)
void gemm_hilo_kernel(const __nv_bfloat16* __restrict__ Ahi,
                      const __nv_bfloat16* __restrict__ Alo,
                      const __nv_bfloat16* __restrict__ Bhi,
                      const __nv_bfloat16* __restrict__ Blo,
                      float* __restrict__ Cout,
                      __nv_bfloat16* __restrict__ Chi,
                      __nv_bfloat16* __restrict__ Clo,
                      int M, int N, int K)
{
    extern __shared__ char dsm[];
    const uint32_t sbase = smem_u32(dsm);
    const int tid = threadIdx.x, lane = tid & 31, wid = tid >> 5;
    const int wm = wid & 3, wn = wid >> 2;
    const int m0 = blockIdx.y * 128, n0 = blockIdx.x * 128;

    const __nv_bfloat16* gAh = Ahi + (size_t)m0 * K;
    const __nv_bfloat16* gAl = Alo + (size_t)m0 * K;
    const __nv_bfloat16* gBh = Bhi + (size_t)n0 * K;
    const __nv_bfloat16* gBl = Blo + (size_t)n0 * K;

    const int lrow = tid >> 1;
    const int lc0  = (tid & 1) * 2;

    float acc[2][8][4];
#pragma unroll
    for (int mt = 0; mt < 2; mt++)
#pragma unroll
        for (int nt = 0; nt < 8; nt++)
#pragma unroll
            for (int r = 0; r < 4; r++) acc[mt][nt][r] = 0.f;

    const int nk = K >> 5;

    auto load_stage = [&](int buf, int kc) {
        const uint32_t st = sbase + buf * STAGE_B;
        const size_t koff = (size_t)kc * 32;
#pragma unroll
        for (int t = 0; t < 2; t++) {
            const int c16 = lc0 + t;
            const uint32_t doff = lrow * 80 + c16 * 16;
            const size_t soff = (size_t)lrow * K + koff + c16 * 8;
            cp16(st + ST_AHI + doff, gAh + soff);
            cp16(st + ST_ALO + doff, gAl + soff);
            cp16(st + ST_BHI + doff, gBh + soff);
            cp16(st + ST_BLO + doff, gBl + soff);
        }
        CP_COMMIT();
    };

    load_stage(0, 0);

    for (int k = 0; k < nk; k++) {
        // Stage k has landed when no groups remain pending (stage k+1 not yet
        // issued at this point).
        asm volatile("cp.async.wait_group 0;" ::: "memory");
        __syncthreads();   // also: every warp done computing iter k-1

        // Overwrites the buffer computed during iter k-1; barrier above makes
        // that safe. Overlaps with compute of stage k below.
        if (k + 1 < nk) load_stage((k + 1) & 1, k + 1);

        const uint32_t st = sbase + (k & 1) * STAGE_B;
#pragma unroll
        for (int ks = 0; ks < 2; ks++) {
            uint32_t ah[2][4], al[2][4];
#pragma unroll
            for (int mt = 0; mt < 2; mt++) {
                const int row = wm * 32 + mt * 16 + (lane & 15);
                const uint32_t off = row * 80 + ks * 32 + ((lane >> 4) << 4);
                ldsm4(ah[mt][0], ah[mt][1], ah[mt][2], ah[mt][3],
                      st + ST_AHI + off);
                ldsm4(al[mt][0], al[mt][1], al[mt][2], al[mt][3],
                      st + ST_ALO + off);
            }
#pragma unroll
            for (int bp = 0; bp < 4; bp++) {
                const int rn = wn * 64 + bp * 16 + ((lane >> 4) << 3) + (lane & 7);
                const uint32_t off = rn * 80 + ks * 32 + (((lane >> 3) & 1) << 4);
                uint32_t bh[4], bl[4];
                ldsm4(bh[0], bh[1], bh[2], bh[3], st + ST_BHI + off);
                ldsm4(bl[0], bl[1], bl[2], bl[3], st + ST_BLO + off);
                // term-major: 4 independent accumulators between reuse
#pragma unroll
                for (int mt = 0; mt < 2; mt++)
#pragma unroll
                    for (int h = 0; h < 2; h++)
                        mma16816(acc[mt][2 * bp + h], ah[mt], bh[2 * h], bh[2 * h + 1]);
#pragma unroll
                for (int mt = 0; mt < 2; mt++)
#pragma unroll
                    for (int h = 0; h < 2; h++)
                        mma16816(acc[mt][2 * bp + h], ah[mt], bl[2 * h], bl[2 * h + 1]);
#pragma unroll
                for (int mt = 0; mt < 2; mt++)
#pragma unroll
                    for (int h = 0; h < 2; h++)
                        mma16816(acc[mt][2 * bp + h], al[mt], bh[2 * h], bh[2 * h + 1]);
            }
        }
    }

    const int lr = lane >> 2, lc = (lane & 3) * 2;
    const int rbase = m0 + wm * 32, cbase = n0 + wn * 64;
    if (Cout) {
#pragma unroll
        for (int mt = 0; mt < 2; mt++) {
#pragma unroll
            for (int nt = 0; nt < 8; nt++) {
                float* d = acc[mt][nt];
                const size_t r0 = (size_t)(rbase + mt * 16 + lr) * N
                                  + cbase + nt * 8 + lc;
                *(float2*)(Cout + r0)         = make_float2(d[0], d[1]);
                *(float2*)(Cout + r0 + 8 * N) = make_float2(d[2], d[3]);
            }
        }
    } else {
#pragma unroll
        for (int mt = 0; mt < 2; mt++) {
#pragma unroll
            for (int nt = 0; nt < 8; nt++) {
                float* d = acc[mt][nt];
#pragma unroll
                for (int half = 0; half < 2; half++) {
                    float v0 = d[half * 2], v1 = d[half * 2 + 1];
                    __nv_bfloat16 h0 = __float2bfloat16(v0);
                    __nv_bfloat16 h1 = __float2bfloat16(v1);
                    __nv_bfloat16 l0 = __float2bfloat16(v0 - __bfloat162float(h0));
                    __nv_bfloat16 l1 = __float2bfloat16(v1 - __bfloat162float(h1));
                    const size_t o = (size_t)(rbase + mt * 16 + lr + half * 8) * N
                                     + cbase + nt * 8 + lc;
                    *(__nv_bfloat162*)(Chi + o) = __nv_bfloat162(h0, h1);
                    *(__nv_bfloat162*)(Clo + o) = __nv_bfloat162(l0, l1);
                }
            }
        }
    }
}

// ---------------------------------------------------------------------------
// fp32 -> bf16 hi/lo elementwise (for x)
// ---------------------------------------------------------------------------
__global__ void convert_hilo_kernel(const float* __restrict__ in,
                                    __nv_bfloat16* __restrict__ hi,
                                    __nv_bfloat16* __restrict__ lo, int n)
{
    int i = blockIdx.x * blockDim.x + threadIdx.x;
    if (i >= n) return;
    float v = in[i];
    __nv_bfloat16 h = __float2bfloat16(v);
    hi[i] = h;
    lo[i] = __float2bfloat16(v - __bfloat162float(h));
}

// ---------------------------------------------------------------------------
// W [Kd,Nd] fp32 -> Wt hi/lo [Nd,Kd] bf16 (tiled transpose)
// ---------------------------------------------------------------------------
__global__ void transpose_hilo_kernel(const float* __restrict__ W,
                                      __nv_bfloat16* __restrict__ hi,
                                      __nv_bfloat16* __restrict__ lo,
                                      int Kd, int Nd)
{
    __shared__ float t[32][33];
    const int tx = threadIdx.x, ty = threadIdx.y;
    const int k0 = blockIdx.y * 32, n0 = blockIdx.x * 32;
#pragma unroll
    for (int i = 0; i < 4; i++)
        t[ty + i * 8][tx] = W[(size_t)(k0 + ty + i * 8) * Nd + n0 + tx];
    __syncthreads();
#pragma unroll
    for (int i = 0; i < 4; i++) {
        float v = t[tx][ty + i * 8];
        __nv_bfloat16 h = __float2bfloat16(v);
        size_t o = (size_t)(n0 + ty + i * 8) * Kd + k0 + tx;
        hi[o] = h;
        lo[o] = __float2bfloat16(v - __bfloat162float(h));
    }
}

// ---------------------------------------------------------------------------
// RoPE on fp32 Q,K -> bf16 hi/lo outputs (fused rope + split)
// ---------------------------------------------------------------------------
__global__ void rope_convert_kernel(const float* __restrict__ Q,
                                    const float* __restrict__ K,
                                    const float* __restrict__ freqs,
                                    __nv_bfloat16* __restrict__ qhi,
                                    __nv_bfloat16* __restrict__ qlo,
                                    __nv_bfloat16* __restrict__ khi,
                                    __nv_bfloat16* __restrict__ klo)
{
    const int total = BATCH * S_LEN * NH * (HD / 2);
    int idx = blockIdx.x * blockDim.x + threadIdx.x;
    if (idx >= total) return;
    int p = idx & 63;
    int s = (idx >> 10) & (S_LEN - 1);
    float f = freqs[s * (HD / 2) + p];
    float sn, cs;
    sincosf(f, &sn, &cs);

    const float2 q = ((const float2*)Q)[idx];
    const float2 k = ((const float2*)K)[idx];
    float q0 = q.x * cs - q.y * sn, q1 = q.x * sn + q.y * cs;
    float k0 = k.x * cs - k.y * sn, k1 = k.x * sn + k.y * cs;

    __nv_bfloat16 qh0 = __float2bfloat16(q0), qh1 = __float2bfloat16(q1);
    __nv_bfloat16 kh0 = __float2bfloat16(k0), kh1 = __float2bfloat16(k1);
    ((__nv_bfloat162*)qhi)[idx] = __nv_bfloat162(qh0, qh1);
    ((__nv_bfloat162*)qlo)[idx] = __nv_bfloat162(
        __float2bfloat16(q0 - __bfloat162float(qh0)),
        __float2bfloat16(q1 - __bfloat162float(qh1)));
    ((__nv_bfloat162*)khi)[idx] = __nv_bfloat162(kh0, kh1);
    ((__nv_bfloat162*)klo)[idx] = __nv_bfloat162(
        __float2bfloat16(k0 - __bfloat162float(kh0)),
        __float2bfloat16(k1 - __bfloat162float(kh1)));
}

// ---------------------------------------------------------------------------
// HMMA causal flash attention, bf16 hi/lo (3-term QK and PV), fp32 softmax.
// BR=BC=64, 128 threads (4 warps x 16 q-rows). Single-buffered K/V smem
// (104KB => 2 CTAs/SM). MMAs term-major within each fragment scope.
// ---------------------------------------------------------------------------
#define FP   136
#define FPB  272
#define FT   17408
#define SQHI 0
#define SQLO 17408
#define SKHI 34816
#define SKLO 52224
#define SVHI 69632
#define SVLO 87040
#define FL_SMEM 104448

__global__ __launch_bounds__(128)
void flash_hmma_kernel(const __nv_bfloat16* __restrict__ Qhi,
                       const __nv_bfloat16* __restrict__ Qlo,
                       const __nv_bfloat16* __restrict__ Khi,
                       const __nv_bfloat16* __restrict__ Klo,
                       const __nv_bfloat16* __restrict__ Vhi,
                       const __nv_bfloat16* __restrict__ Vlo,
                       __nv_bfloat16* __restrict__ Ohi,
                       __nv_bfloat16* __restrict__ Olo)
{
    extern __shared__ char dsm[];
    const uint32_t sb = smem_u32(dsm);

    const int tid = threadIdx.x, lane = tid & 31, wm = tid >> 5;
    const int lr = lane >> 2, lc2 = (lane & 3) * 2;

    const int bh_ = blockIdx.y;
    const int b = bh_ >> 4, head = bh_ & 15;
    const int qi = gridDim.x - 1 - blockIdx.x;       // heavy blocks first
    const int q0 = qi * 64;
    const size_t base = ((size_t)b * S_LEN) * D_DIM + head * HD;

#pragma unroll
    for (int j = 0; j < 8; j++) {
        int lin = j * 128 + tid;
        int row = lin >> 4, c16 = lin & 15;
        const size_t so = base + (size_t)(q0 + row) * D_DIM + c16 * 8;
        const uint32_t doff = row * FPB + c16 * 16;
        cp16(sb + SQHI + doff, Qhi + so);
        cp16(sb + SQLO + doff, Qlo + so);
    }
    CP_COMMIT();

    float m[2] = {-1e30f, -1e30f}, l[2] = {0.f, 0.f};
    float accO[16][4];
#pragma unroll
    for (int nt = 0; nt < 16; nt++)
#pragma unroll
        for (int e = 0; e < 4; e++) accO[nt][e] = 0.f;

    const float scale = 0.08838834764831845f;
    const int qrow_base = q0 + wm * 16;

    for (int kt = 0; kt <= qi; kt++) {
        const int k0g = kt * 64;
        __syncthreads();
#pragma unroll
        for (int j = 0; j < 8; j++) {
            int lin = j * 128 + tid;
            int row = lin >> 4, c16 = lin & 15;
            const size_t so = base + (size_t)(k0g + row) * D_DIM + c16 * 8;
            const uint32_t doff = row * FPB + c16 * 16;
            cp16(sb + SKHI + doff, Khi + so);
            cp16(sb + SKLO + doff, Klo + so);
            cp16(sb + SVHI + doff, Vhi + so);
            cp16(sb + SVLO + doff, Vlo + so);
        }
        CP_COMMIT();
        asm volatile("cp.async.wait_group 0;" ::: "memory");
        __syncthreads();

        float accS[8][4];
#pragma unroll
        for (int n = 0; n < 8; n++)
#pragma unroll
            for (int e = 0; e < 4; e++) accS[n][e] = 0.f;

#pragma unroll
        for (int ks = 0; ks < 8; ks++) {
            const int kk = ks * 16;
            uint32_t qh[4], ql[4];
            const uint32_t qoff = (wm * 16 + (lane & 15)) * FPB
                                  + (kk + ((lane >> 4) << 3)) * 2;
            ldsm4(qh[0], qh[1], qh[2], qh[3], sb + SQHI + qoff);
            ldsm4(ql[0], ql[1], ql[2], ql[3], sb + SQLO + qoff);
#pragma unroll
            for (int np = 0; np < 4; np++) {
                const uint32_t koff =
                    (np * 16 + (lane & 7) + ((lane >> 4) << 3)) * FPB
                    + (kk + (((lane >> 3) & 1) << 3)) * 2;
                uint32_t bh[4], bl[4];
                ldsm4(bh[0], bh[1], bh[2], bh[3], sb + SKHI + koff);
                ldsm4(bl[0], bl[1], bl[2], bl[3], sb + SKLO + koff);
                // term-major over the 2 accumulators of this np
#pragma unroll
                for (int t = 0; t < 2; t++)
                    mma16816(accS[np * 2 + t], qh, bh[2 * t], bh[2 * t + 1]);
#pragma unroll
                for (int t = 0; t < 2; t++)
                    mma16816(accS[np * 2 + t], qh, bl[2 * t], bl[2 * t + 1]);
#pragma unroll
                for (int t = 0; t < 2; t++)
                    mma16816(accS[np * 2 + t], ql, bh[2 * t], bh[2 * t + 1]);
            }
        }

        const bool diag = (kt == qi);
#pragma unroll
        for (int n = 0; n < 8; n++) {
#pragma unroll
            for (int e = 0; e < 4; e++) {
                float v = accS[n][e] * scale;
                if (diag) {
                    int row = qrow_base + lr + 8 * (e >> 1);
                    int col = k0g + n * 8 + lc2 + (e & 1);
                    if (col > row) v = -1e30f;
                }
                accS[n][e] = v;
            }
        }

#pragma unroll
        for (int h = 0; h < 2; h++) {
            float mt = -1e30f;
#pragma unroll
            for (int n = 0; n < 8; n++)
                mt = fmaxf(mt, fmaxf(accS[n][2 * h], accS[n][2 * h + 1]));
            mt = fmaxf(mt, __shfl_xor_sync(0xffffffffu, mt, 1));
            mt = fmaxf(mt, __shfl_xor_sync(0xffffffffu, mt, 2));
            float mn = fmaxf(m[h], mt);
            float alpha = __expf(m[h] - mn);
            m[h] = mn;
            float lt = 0.f;
#pragma unroll
            for (int n = 0; n < 8; n++) {
                float p0 = __expf(accS[n][2 * h] - mn);
                float p1 = __expf(accS[n][2 * h + 1] - mn);
                accS[n][2 * h] = p0;
                accS[n][2 * h + 1] = p1;
                lt += p0 + p1;
            }
            lt += __shfl_xor_sync(0xffffffffu, lt, 1);
            lt += __shfl_xor_sync(0xffffffffu, lt, 2);
            l[h] = l[h] * alpha + lt;
#pragma unroll
            for (int nt = 0; nt < 16; nt++) {
                accO[nt][2 * h] *= alpha;
                accO[nt][2 * h + 1] *= alpha;
            }
        }

#pragma unroll
        for (int t = 0; t < 4; t++) {
            uint32_t phi[4], plo[4];
#pragma unroll
            for (int half = 0; half < 2; half++) {
                float* s = accS[2 * t + half];
#pragma unroll
                for (int rh = 0; rh < 2; rh++) {
                    float v0 = s[2 * rh], v1 = s[2 * rh + 1];
                    __nv_bfloat16 h0 = __float2bfloat16(v0);
                    __nv_bfloat16 h1 = __float2bfloat16(v1);
                    phi[half * 2 + rh] = packbf2(h0, h1);
                    plo[half * 2 + rh] = packbf2(
                        __float2bfloat16(v0 - __bfloat162float(h0)),
                        __float2bfloat16(v1 - __bfloat162float(h1)));
                }
            }
            const int kk = t * 16;
#pragma unroll
            for (int np = 0; np < 8; np++) {
                const uint32_t voff = (kk + (lane & 15)) * FPB
                                      + (np * 16 + ((lane >> 4) << 3)) * 2;
                uint32_t vh[4], vl[4];
                ldsm4t(vh[0], vh[1], vh[2], vh[3], sb + SVHI + voff);
                ldsm4t(vl[0], vl[1], vl[2], vl[3], sb + SVLO + voff);
                // term-major over the 2 accumulators of this np
#pragma unroll
                for (int u = 0; u < 2; u++)
                    mma16816(accO[np * 2 + u], phi, vh[2 * u], vh[2 * u + 1]);
#pragma unroll
                for (int u = 0; u < 2; u++)
                    mma16816(accO[np * 2 + u], phi, vl[2 * u], vl[2 * u + 1]);
#pragma unroll
                for (int u = 0; u < 2; u++)
                    mma16816(accO[np * 2 + u], plo, vh[2 * u], vh[2 * u + 1]);
            }
        }
    }

    const float inv0 = 1.0f / l[0], inv1 = 1.0f / l[1];
#pragma unroll
    for (int nt = 0; nt < 16; nt++) {
#pragma unroll
        for (int h = 0; h < 2; h++) {
            float inv = h ? inv1 : inv0;
            float v0 = accO[nt][2 * h] * inv;
            float v1 = accO[nt][2 * h + 1] * inv;
            __nv_bfloat16 h0 = __float2bfloat16(v0);
            __nv_bfloat16 h1 = __float2bfloat16(v1);
            const size_t o = base
                + (size_t)(qrow_base + lr + 8 * h) * D_DIM + nt * 8 + lc2;
            *(uint32_t*)(Ohi + o) = packbf2(h0, h1);
            *(uint32_t*)(Olo + o) = packbf2(
                __float2bfloat16(v0 - __bfloat162float(h0)),
                __float2bfloat16(v1 - __bfloat162float(h1)));
        }
    }
}

// ---------------------------------------------------------------------------
// Launch
// Inputs: x, freqs, mask(unused: exactly causal), Wq, Wdown, Wkup, Wvup, Wo
// ---------------------------------------------------------------------------
extern "C" void kernel_launch(void* const* d_in, const int* in_sizes, int n_in,
                              void* d_out, int out_size)
{
    const float* x     = (const float*)d_in[0];
    const float* freqs = (const float*)d_in[1];
    const float* Wq    = (const float*)d_in[3];
    const float* Wdn   = (const float*)d_in[4];
    const float* Wku   = (const float*)d_in[5];
    const float* Wvu   = (const float*)d_in[6];
    const float* Wo    = (const float*)d_in[7];
    float* out = (float*)d_out;

    float *Qb, *Kb;
    __nv_bfloat16 *xhi, *xlo, *chi, *clo, *wthi, *wtlo;
    __nv_bfloat16 *qhi, *qlo, *khi, *klo, *vhi, *vlo, *ohi, *olo;
    cudaGetSymbolAddress((void**)&Qb, g_Q);
    cudaGetSymbolAddress((void**)&Kb, g_K);
    cudaGetSymbolAddress((void**)&xhi, g_xhi);
    cudaGetSymbolAddress((void**)&xlo, g_xlo);
    cudaGetSymbolAddress((void**)&chi, g_chi);
    cudaGetSymbolAddress((void**)&clo, g_clo);
    cudaGetSymbolAddress((void**)&qhi, g_qhi);
    cudaGetSymbolAddress((void**)&qlo, g_qlo);
    cudaGetSymbolAddress((void**)&khi, g_khi);
    cudaGetSymbolAddress((void**)&klo, g_klo);
    cudaGetSymbolAddress((void**)&vhi, g_vhi);
    cudaGetSymbolAddress((void**)&vlo, g_vlo);
    cudaGetSymbolAddress((void**)&ohi, g_ohi);
    cudaGetSymbolAddress((void**)&olo, g_olo);
    cudaGetSymbolAddress((void**)&wthi, g_wthi);
    cudaGetSymbolAddress((void**)&wtlo, g_wtlo);

    cudaFuncSetAttribute(gemm_hilo_kernel,
                         cudaFuncAttributeMaxDynamicSharedMemorySize, GK_SMEM_DYN);
    cudaFuncSetAttribute(flash_hmma_kernel,
                         cudaFuncAttributeMaxDynamicSharedMemorySize, FL_SMEM);

    // Weight transposes + x conversion (bandwidth-bound)
    dim3 tb(32, 8);
    transpose_hilo_kernel<<<dim3(64, 64), tb>>>(Wq,  wthi + OFF_WQ,  wtlo + OFF_WQ,  2048, 2048);
    transpose_hilo_kernel<<<dim3(16, 64), tb>>>(Wdn, wthi + OFF_WDN, wtlo + OFF_WDN, 2048, 512);
    transpose_hilo_kernel<<<dim3(64, 16), tb>>>(Wku, wthi + OFF_WKU, wtlo + OFF_WKU, 512, 2048);
    transpose_hilo_kernel<<<dim3(64, 16), tb>>>(Wvu, wthi + OFF_WVU, wtlo + OFF_WVU, 512, 2048);
    transpose_hilo_kernel<<<dim3(64, 64), tb>>>(Wo,  wthi + OFF_WO,  wtlo + OFF_WO,  2048, 2048);

    const int nx = ROWS_TOT * D_DIM;
    convert_hilo_kernel<<<nx / 256, 256>>>(x, xhi, xlo, nx);

    // Projections (HMMA bf16 hi/lo, fp32 accum)
    gemm_hilo_kernel<<<dim3(16, 32), 256, GK_SMEM_DYN>>>(
        xhi, xlo, wthi + OFF_WQ, wtlo + OFF_WQ, Qb, nullptr, nullptr,
        ROWS_TOT, D_DIM, D_DIM);
    gemm_hilo_kernel<<<dim3(4, 32), 256, GK_SMEM_DYN>>>(
        xhi, xlo, wthi + OFF_WDN, wtlo + OFF_WDN, nullptr, chi, clo,
        ROWS_TOT, LAT, D_DIM);
    gemm_hilo_kernel<<<dim3(16, 32), 256, GK_SMEM_DYN>>>(
        chi, clo, wthi + OFF_WKU, wtlo + OFF_WKU, Kb, nullptr, nullptr,
        ROWS_TOT, D_DIM, LAT);
    gemm_hilo_kernel<<<dim3(16, 32), 256, GK_SMEM_DYN>>>(
        chi, clo, wthi + OFF_WVU, wtlo + OFF_WVU, nullptr, vhi, vlo,
        ROWS_TOT, D_DIM, LAT);

    // RoPE + bf16 hi/lo split for Q,K
    const int pairs = BATCH * S_LEN * NH * (HD / 2);
    rope_convert_kernel<<<(pairs + 255) / 256, 256>>>(
        Qb, Kb, freqs, qhi, qlo, khi, klo);

    // Flash attention (causal, HMMA hi/lo) -> O as bf16 hi/lo
    flash_hmma_kernel<<<dim3(S_LEN / 64, BATCH * NH), 128, FL_SMEM>>>(
        qhi, qlo, khi, klo, vhi, vlo, ohi, olo);

    // Output projection
    gemm_hilo_kernel<<<dim3(16, 32), 256, GK_SMEM_DYN>>>(
        ohi, olo, wthi + OFF_WO, wtlo + OFF_WO, out, nullptr, nullptr,
        ROWS_TOT, D_DIM, D_DIM);
}